// round 4
// baseline (speedup 1.0000x reference)
#include <cuda_runtime.h>
#include <cstdint>

// ---------------------------------------------------------------------------
// GraphSAGE via mma.sync tf32 (portable PTX; tcgen05 rejected by sm_103 ptxas).
// B=1024, F=D=256, OUT=128, EXP=[10,25].
// Big kernel: CTA tile 128x128, K-chunk 64, double-buffered smem, 1 barrier/chunk.
// Small kernel: CTA tile 64x64 for the M=1024 projections (parallelism).
// ---------------------------------------------------------------------------

#define THREADS 256
#define LDK 64                     // K-chunk (floats)
#define LDA 68                     // smem row stride (floats): (4r+c)%32 conflict-free
#define STAGE_B (128 * LDA * 4)    // one stage buffer: 34816 B
#define EPI_STRIDE 132
#define SMEM_BIG (1024 + 4 * STAGE_B)          // msk | As0 As1 Bs0 Bs1 = 140288 B

#define S_LDA 36
#define S_STAGE (64 * S_LDA * 4)               // 9216 B
#define SMEM_SMALL (4 * S_STAGE)               // 36864 B

// Scratch (static device globals — no allocation allowed)
__device__ float g_pool1 [10240 * 256];
__device__ float g_pool0 [1024  * 256];
__device__ float g_state1[10240 * 512];
__device__ float g_state0[1024  * 512];
__device__ float g_pooled[1024  * 256];
__device__ float g_fin   [1024  * 512];

__device__ __forceinline__ float tf32_rn(float x) {
    uint32_t r;
    asm("cvt.rna.tf32.f32 %0, %1;" : "=r"(r) : "f"(x));
    return __uint_as_float(r);
}

__device__ __forceinline__ void mma8(float* c, const uint32_t* a, const uint32_t* b) {
    asm volatile(
        "mma.sync.aligned.m16n8k8.row.col.f32.tf32.tf32.f32 "
        "{%0,%1,%2,%3}, {%4,%5,%6,%7}, {%8,%9}, {%0,%1,%2,%3};"
        : "+f"(c[0]), "+f"(c[1]), "+f"(c[2]), "+f"(c[3])
        : "r"(a[0]), "r"(a[1]), "r"(a[2]), "r"(a[3]), "r"(b[0]), "r"(b[1]));
}

// ---------------------------------------------------------------------------
// Big kernel: Y = X @ W^T, CTA tile 128(M) x 128(N), warp tile 32x64.
//   S==0: plain GEMM -> Y[row*ldy + blockIdx.y*128 + n]
//   S>0 : fused masked-relu-max pool over groups of S rows
//         -> Y[group*256 + blockIdx.y*128 + n]; padded rows mask=0 (exact).
// ---------------------------------------------------------------------------
template <int S>
__global__ __launch_bounds__(THREADS) void mma_big(
    const float* __restrict__ X, const float* __restrict__ W,
    const float* __restrict__ mask, float* __restrict__ Y,
    int K, int Mtot, int ldy)
{
    constexpr int RPC = (S == 25) ? 125 : (S == 10) ? 120 : 128;
    constexpr int GPC = S ? RPC / S : 0;

    extern __shared__ char smem[];
    float* msk = (float*)smem;                        // [128]
    float* buf = (float*)(smem + 1024);               // epilogue reuse
    float* St[4] = { (float*)(smem + 1024),                    // As0
                     (float*)(smem + 1024 + STAGE_B),          // As1
                     (float*)(smem + 1024 + 2 * STAGE_B),      // Bs0
                     (float*)(smem + 1024 + 3 * STAGE_B) };    // Bs1

    const int t    = threadIdx.x;
    const int lane = t & 31;
    const int warp = t >> 5;
    const int wm   = warp >> 1;            // 0..3
    const int wn   = warp & 1;             // 0..1
    const int tr   = lane >> 2;            // 0..7
    const int tc   = lane & 3;             // 0..3

    const int row0 = blockIdx.x * RPC;
    const float* Wb = W + (size_t)blockIdx.y * 128 * K;

    if (S && t < 128) {
        int rg = row0 + t;
        msk[t] = (t < RPC && rg < Mtot) ? mask[rg] : 0.f;
    }

    // staging map: 128 rows x 16 float4 per buffer; 8 float4 per thread
    const int ldrow = t >> 4;              // 0..15
    const int ldc4  = t & 15;              // 0..15

    float4 pa[8], pb[8];
    auto prefetch = [&](int k0) {
#pragma unroll
        for (int j = 0; j < 8; j++) {
            int row = ldrow + j * 16;
            int rg = row0 + row;
            pa[j] = (rg < Mtot)
                ? *(const float4*)(X + (size_t)rg * K + k0 + ldc4 * 4)
                : make_float4(0.f, 0.f, 0.f, 0.f);
            pb[j] = *(const float4*)(Wb + (size_t)row * K + k0 + ldc4 * 4);
        }
    };
    auto stage = [&](int b) {
        float* As = St[b];
        float* Bs = St[2 + b];
#pragma unroll
        for (int j = 0; j < 8; j++) {
            int row = ldrow + j * 16;
            float4 va = pa[j], vb = pb[j];
            va.x = tf32_rn(va.x); va.y = tf32_rn(va.y);
            va.z = tf32_rn(va.z); va.w = tf32_rn(va.w);
            vb.x = tf32_rn(vb.x); vb.y = tf32_rn(vb.y);
            vb.z = tf32_rn(vb.z); vb.w = tf32_rn(vb.w);
            *(float4*)(As + row * LDA + ldc4 * 4) = va;
            *(float4*)(Bs + row * LDA + ldc4 * 4) = vb;
        }
    };

    float acc[2][8][4];
#pragma unroll
    for (int mt = 0; mt < 2; mt++)
#pragma unroll
        for (int nt = 0; nt < 8; nt++)
#pragma unroll
            for (int i = 0; i < 4; i++) acc[mt][nt][i] = 0.f;

    const int NC = K / LDK;
    const int arow = wm * 32 + tr;
    const int brow = wn * 64 + tr;

    prefetch(0);
    stage(0);
    __syncthreads();

    for (int c = 0; c < NC; c++) {
        const int b = c & 1;
        if (c + 1 < NC) prefetch((c + 1) * LDK);

        const float* As = St[b];
        const float* Bs = St[2 + b];
#pragma unroll
        for (int ks = 0; ks < LDK / 8; ks++) {
            const int k = ks * 8 + tc;
            uint32_t af[2][4], bf[8][2];
#pragma unroll
            for (int mt = 0; mt < 2; mt++) {
                const float* p = As + (arow + mt * 16) * LDA + k;
                af[mt][0] = __float_as_uint(p[0]);
                af[mt][1] = __float_as_uint(p[8 * LDA]);
                af[mt][2] = __float_as_uint(p[4]);
                af[mt][3] = __float_as_uint(p[8 * LDA + 4]);
            }
#pragma unroll
            for (int nt = 0; nt < 8; nt++) {
                const float* p = Bs + (brow + nt * 8) * LDA + k;
                bf[nt][0] = __float_as_uint(p[0]);
                bf[nt][1] = __float_as_uint(p[4]);
            }
#pragma unroll
            for (int mt = 0; mt < 2; mt++)
#pragma unroll
                for (int nt = 0; nt < 8; nt++)
                    mma8(acc[mt][nt], af[mt], bf[nt]);
        }

        if (c + 1 < NC) stage(b ^ 1);
        __syncthreads();
    }

    if (S == 0) {
        const int cb = blockIdx.y * 128 + wn * 64;
#pragma unroll
        for (int mt = 0; mt < 2; mt++) {
            const int r0 = row0 + wm * 32 + mt * 16 + tr;
#pragma unroll
            for (int nt = 0; nt < 8; nt++) {
                const int c0 = cb + nt * 8 + 2 * tc;
                if (r0 < Mtot)
                    *(float2*)(Y + (size_t)r0 * ldy + c0) =
                        make_float2(acc[mt][nt][0], acc[mt][nt][1]);
                if (r0 + 8 < Mtot)
                    *(float2*)(Y + (size_t)(r0 + 8) * ldy + c0) =
                        make_float2(acc[mt][nt][2], acc[mt][nt][3]);
            }
        }
    } else {
#pragma unroll
        for (int mt = 0; mt < 2; mt++) {
            const int rr = wm * 32 + mt * 16 + tr;
            const float m0 = msk[rr], m1 = msk[rr + 8];
#pragma unroll
            for (int nt = 0; nt < 8; nt++) {
                const int cc = wn * 64 + nt * 8 + 2 * tc;
                buf[rr * EPI_STRIDE + cc]           = fmaxf(acc[mt][nt][0], 0.f) * m0;
                buf[rr * EPI_STRIDE + cc + 1]       = fmaxf(acc[mt][nt][1], 0.f) * m0;
                buf[(rr + 8) * EPI_STRIDE + cc]     = fmaxf(acc[mt][nt][2], 0.f) * m1;
                buf[(rr + 8) * EPI_STRIDE + cc + 1] = fmaxf(acc[mt][nt][3], 0.f) * m1;
            }
        }
        __syncthreads();
        const int G = Mtot / S;
        for (int tt = t; tt < GPC * 128; tt += THREADS) {
            const int g = tt >> 7, cc = tt & 127;
            const int og = blockIdx.x * GPC + g;
            if (og < G) {
                float m = 0.f;
#pragma unroll
                for (int r = 0; r < S; r++)
                    m = fmaxf(m, buf[(g * S + r) * EPI_STRIDE + cc]);
                Y[(size_t)og * 256 + blockIdx.y * 128 + cc] = m;
            }
        }
    }
}

// ---------------------------------------------------------------------------
// Small GEMM: CTA tile 64x64, 128 threads, warp tile 32x32, K-chunk 32,
// double-buffered. For the M=1024 projections (needs many CTAs for the chip).
// ---------------------------------------------------------------------------
__global__ __launch_bounds__(128) void mma_small(
    const float* __restrict__ X, const float* __restrict__ W,
    float* __restrict__ Y, int K, int Mtot, int ldy)
{
    extern __shared__ char smem[];
    float* St[4] = { (float*)smem,                       // As0
                     (float*)(smem + S_STAGE),           // As1
                     (float*)(smem + 2 * S_STAGE),       // Bs0
                     (float*)(smem + 3 * S_STAGE) };     // Bs1

    const int t    = threadIdx.x;
    const int lane = t & 31;
    const int warp = t >> 5;
    const int wm   = warp >> 1;          // 0..1
    const int wn   = warp & 1;           // 0..1
    const int tr   = lane >> 2;
    const int tc   = lane & 3;

    const int row0 = blockIdx.x * 64;
    const float* Wb = W + (size_t)blockIdx.y * 64 * K;

    const int ldrow = t >> 3;            // 0..15
    const int ldc4  = t & 7;             // 0..7

    float4 pa[4], pb[4];
    auto prefetch = [&](int k0) {
#pragma unroll
        for (int j = 0; j < 4; j++) {
            int row = ldrow + j * 16;
            int rg = row0 + row;
            pa[j] = (rg < Mtot)
                ? *(const float4*)(X + (size_t)rg * K + k0 + ldc4 * 4)
                : make_float4(0.f, 0.f, 0.f, 0.f);
            pb[j] = *(const float4*)(Wb + (size_t)row * K + k0 + ldc4 * 4);
        }
    };
    auto stage = [&](int b) {
        float* As = St[b];
        float* Bs = St[2 + b];
#pragma unroll
        for (int j = 0; j < 4; j++) {
            int row = ldrow + j * 16;
            float4 va = pa[j], vb = pb[j];
            va.x = tf32_rn(va.x); va.y = tf32_rn(va.y);
            va.z = tf32_rn(va.z); va.w = tf32_rn(va.w);
            vb.x = tf32_rn(vb.x); vb.y = tf32_rn(vb.y);
            vb.z = tf32_rn(vb.z); vb.w = tf32_rn(vb.w);
            *(float4*)(As + row * S_LDA + ldc4 * 4) = va;
            *(float4*)(Bs + row * S_LDA + ldc4 * 4) = vb;
        }
    };

    float acc[2][4][4];
#pragma unroll
    for (int mt = 0; mt < 2; mt++)
#pragma unroll
        for (int nt = 0; nt < 4; nt++)
#pragma unroll
            for (int i = 0; i < 4; i++) acc[mt][nt][i] = 0.f;

    const int NC = K >> 5;
    const int arow = wm * 32 + tr;
    const int brow = wn * 32 + tr;

    prefetch(0);
    stage(0);
    __syncthreads();

    for (int c = 0; c < NC; c++) {
        const int b = c & 1;
        if (c + 1 < NC) prefetch((c + 1) << 5);

        const float* As = St[b];
        const float* Bs = St[2 + b];
#pragma unroll
        for (int ks = 0; ks < 4; ks++) {
            const int k = ks * 8 + tc;
            uint32_t af[2][4], bf[4][2];
#pragma unroll
            for (int mt = 0; mt < 2; mt++) {
                const float* p = As + (arow + mt * 16) * S_LDA + k;
                af[mt][0] = __float_as_uint(p[0]);
                af[mt][1] = __float_as_uint(p[8 * S_LDA]);
                af[mt][2] = __float_as_uint(p[4]);
                af[mt][3] = __float_as_uint(p[8 * S_LDA + 4]);
            }
#pragma unroll
            for (int nt = 0; nt < 4; nt++) {
                const float* p = Bs + (brow + nt * 8) * S_LDA + k;
                bf[nt][0] = __float_as_uint(p[0]);
                bf[nt][1] = __float_as_uint(p[4]);
            }
#pragma unroll
            for (int mt = 0; mt < 2; mt++)
#pragma unroll
                for (int nt = 0; nt < 4; nt++)
                    mma8(acc[mt][nt], af[mt], bf[nt]);
        }

        if (c + 1 < NC) stage(b ^ 1);
        __syncthreads();
    }

    const int cb = blockIdx.y * 64 + wn * 32;
#pragma unroll
    for (int mt = 0; mt < 2; mt++) {
        const int r0 = row0 + wm * 32 + mt * 16 + tr;
#pragma unroll
        for (int nt = 0; nt < 4; nt++) {
            const int c0 = cb + nt * 8 + 2 * tc;
            if (r0 < Mtot)
                *(float2*)(Y + (size_t)r0 * ldy + c0) =
                    make_float2(acc[mt][nt][0], acc[mt][nt][1]);
            if (r0 + 8 < Mtot)
                *(float2*)(Y + (size_t)(r0 + 8) * ldy + c0) =
                    make_float2(acc[mt][nt][2], acc[mt][nt][3]);
        }
    }
}

// ---------------------------------------------------------------------------
// Host driver — 10 graph-capturable launches.
// ---------------------------------------------------------------------------
extern "C" void kernel_launch(void* const* d_in, const int* in_sizes, int n_in,
                              void* d_out, int out_size)
{
    const float* h0    = (const float*)d_in[0];
    const float* h1    = (const float*)d_in[1];
    const float* h2    = (const float*)d_in[2];
    const float* mask0 = (const float*)d_in[3];
    const float* mask1 = (const float*)d_in[4];
    const float* Ws0   = (const float*)d_in[5];
    const float* Wn0   = (const float*)d_in[6];
    const float* Wp0   = (const float*)d_in[7];
    const float* Ws1   = (const float*)d_in[8];
    const float* Wn1   = (const float*)d_in[9];
    const float* Wp1   = (const float*)d_in[10];
    const float* Wout  = (const float*)d_in[11];
    float* out = (float*)d_out;

    float *pool1, *pool0, *state1, *state0, *pooled, *fin;
    cudaGetSymbolAddress((void**)&pool1,  g_pool1);
    cudaGetSymbolAddress((void**)&pool0,  g_pool0);
    cudaGetSymbolAddress((void**)&state1, g_state1);
    cudaGetSymbolAddress((void**)&state0, g_state0);
    cudaGetSymbolAddress((void**)&pooled, g_pooled);
    cudaGetSymbolAddress((void**)&fin,    g_fin);

    cudaFuncSetAttribute(mma_big<25>, cudaFuncAttributeMaxDynamicSharedMemorySize, SMEM_BIG);
    cudaFuncSetAttribute(mma_big<10>, cudaFuncAttributeMaxDynamicSharedMemorySize, SMEM_BIG);
    cudaFuncSetAttribute(mma_big<0>,  cudaFuncAttributeMaxDynamicSharedMemorySize, SMEM_BIG);
    cudaFuncSetAttribute(mma_small,   cudaFuncAttributeMaxDynamicSharedMemorySize, SMEM_SMALL);

    const int B = 1024;

    // ---- layer 0 ----
    // pool1 = maxpool_25 relu(h2 @ Wn0^T) * mask1      (B*10, 256)
    mma_big<25><<<dim3(2048, 2), THREADS, SMEM_BIG>>>(h2, Wn0, mask1, pool1, 256, B * 250, 0);
    // pool0 = maxpool_10 relu(h1 @ Wn0^T) * mask0      (B, 256)
    mma_big<10><<<dim3(86, 2), THREADS, SMEM_BIG>>>(h1, Wn0, mask0, pool0, 256, B * 10, 0);

    // state1 = concat( h1 @ Ws0^T , pool1 @ Wp0^T )    (B*10, 512)
    mma_big<0><<<dim3(80, 2), THREADS, SMEM_BIG>>>(h1,    Ws0, nullptr, state1,       256, B * 10, 512);
    mma_big<0><<<dim3(80, 2), THREADS, SMEM_BIG>>>(pool1, Wp0, nullptr, state1 + 256, 256, B * 10, 512);

    // state0 = concat( h0 @ Ws0^T , pool0 @ Wp0^T )    (B, 512)
    mma_small<<<dim3(16, 4), 128, SMEM_SMALL>>>(h0,    Ws0, state0,       256, B, 512);
    mma_small<<<dim3(16, 4), 128, SMEM_SMALL>>>(pool0, Wp0, state0 + 256, 256, B, 512);

    // ---- layer 1 ----
    // pooled = maxpool_10 relu(state1 @ Wn1^T) * mask0 (B, 256), K=512
    mma_big<10><<<dim3(86, 2), THREADS, SMEM_BIG>>>(state1, Wn1, mask0, pooled, 512, B * 10, 0);

    // fin = concat( state0 @ Ws1^T , pooled @ Wp1^T )  (B, 512)
    mma_small<<<dim3(16, 4), 128, SMEM_SMALL>>>(state0, Ws1, fin,       512, B, 512);
    mma_small<<<dim3(16, 4), 128, SMEM_SMALL>>>(pooled, Wp1, fin + 256, 256, B, 512);

    // ---- output ----
    mma_small<<<dim3(16, 2), 128, SMEM_SMALL>>>(fin, Wout, out, 512, B, 128);
}

// round 7
// speedup vs baseline: 1.8474x; 1.8474x over previous
#include <cuda_runtime.h>
#include <cuda_fp16.h>
#include <cstdint>

// ---------------------------------------------------------------------------
// GraphSAGE via mma.sync fp16 (f32 accumulate). B=1024, F=D=256, OUT=128,
// EXP=[10,25]. Big kernel: CTA 128x128, K-chunk 32, double-buffered fp16
// smem stages, 1 barrier/chunk. Fused masked-relu-max pooling in epilogue.
// Grid: x = N-half (shares M-tile A reads via L2), y = M-tile.
// ---------------------------------------------------------------------------

#define LDH 36                                   // halves per smem row (stride)
#define STAGE_H (128 * LDH * 2)                  // 9216 B per stage buffer
#define EPI_STRIDE 132
#define SMEM_BIG (1024 + 128 * EPI_STRIDE * 4)   // 1024 ctrl | max(stages, epi)

#define S_STAGE_H (64 * LDH * 2)                 // 4608 B
#define SMEM_SMALL (4 * S_STAGE_H)               // 18432 B

// Scratch (static device globals — no allocation allowed)
__device__ float g_pool1 [10240 * 256];
__device__ float g_pool0 [1024  * 256];
__device__ float g_state1[10240 * 512];
__device__ float g_state0[1024  * 512];
__device__ float g_pooled[1024  * 256];
__device__ float g_fin   [1024  * 512];

__device__ __forceinline__ uint32_t h2u(__half2 h) {
    return *reinterpret_cast<uint32_t*>(&h);
}

__device__ __forceinline__ void mma16(float* c, const uint32_t* a, const uint32_t* b) {
    asm volatile(
        "mma.sync.aligned.m16n8k16.row.col.f32.f16.f16.f32 "
        "{%0,%1,%2,%3}, {%4,%5,%6,%7}, {%8,%9}, {%0,%1,%2,%3};"
        : "+f"(c[0]), "+f"(c[1]), "+f"(c[2]), "+f"(c[3])
        : "r"(a[0]), "r"(a[1]), "r"(a[2]), "r"(a[3]), "r"(b[0]), "r"(b[1]));
}

// ---------------------------------------------------------------------------
// Big kernel: Y = X @ W^T. CTA tile 128(M) x 128(N), warp tile 32x64.
//   blockIdx.x = N-half (0/1), blockIdx.y = M tile.
//   S==0: plain GEMM -> Y[row*ldy + bx*128 + n]
//   S>0 : fused masked-relu-max pool over groups of S rows
//         -> Y[group*256 + bx*128 + n]; padded rows mask=0 (exact: all
//         pooled candidates are >= 0).
// ---------------------------------------------------------------------------
template <int S>
__global__ __launch_bounds__(256, 2) void mma_big(
    const float* __restrict__ X, const float* __restrict__ W,
    const float* __restrict__ mask, float* __restrict__ Y,
    int K, int Mtot, int ldy)
{
    constexpr int RPC = (S == 25) ? 125 : (S == 10) ? 120 : 128;
    constexpr int GPC = S ? RPC / S : 0;

    extern __shared__ char smem[];
    float* msk = (float*)smem;                     // [128]
    float* buf = (float*)(smem + 1024);            // epilogue reuse (fp32)
    __half* Ast[2] = { (__half*)(smem + 1024),
                       (__half*)(smem + 1024 + STAGE_H) };
    __half* Bst[2] = { (__half*)(smem + 1024 + 2 * STAGE_H),
                       (__half*)(smem + 1024 + 3 * STAGE_H) };

    const int t    = threadIdx.x;
    const int lane = t & 31;
    const int warp = t >> 5;
    const int wm   = warp >> 1;              // 0..3
    const int wn   = warp & 1;               // 0..1
    const int tr   = lane >> 2;              // 0..7
    const int tc   = lane & 3;               // 0..3

    const int row0 = blockIdx.y * RPC;
    const float* Wb = W + (size_t)blockIdx.x * 128 * K;

    if (S && t < 128) {
        int rg = row0 + t;
        msk[t] = (t < RPC && rg < Mtot) ? mask[rg] : 0.f;
    }

    // staging: 128 rows x 8 float4-sources; 4 per thread
    const int ldrow = t >> 3;                // 0..31 (+ j*32)
    const int ldc4  = t & 7;                 // 0..7

    uint2 pa[4], pb[4];                      // converted half2 pairs
    auto prefetch = [&](int k0) {
#pragma unroll
        for (int j = 0; j < 4; j++) {
            int row = ldrow + j * 32;
            int rg = row0 + row;
            float4 va = (rg < Mtot)
                ? *(const float4*)(X + (size_t)rg * K + k0 + ldc4 * 4)
                : make_float4(0.f, 0.f, 0.f, 0.f);
            float4 vb = *(const float4*)(Wb + (size_t)row * K + k0 + ldc4 * 4);
            pa[j] = make_uint2(h2u(__floats2half2_rn(va.x, va.y)),
                               h2u(__floats2half2_rn(va.z, va.w)));
            pb[j] = make_uint2(h2u(__floats2half2_rn(vb.x, vb.y)),
                               h2u(__floats2half2_rn(vb.z, vb.w)));
        }
    };
    auto stage = [&](int b) {
        __half* As = Ast[b];
        __half* Bs = Bst[b];
#pragma unroll
        for (int j = 0; j < 4; j++) {
            int row = ldrow + j * 32;
            *(uint2*)(As + row * LDH + ldc4 * 4) = pa[j];
            *(uint2*)(Bs + row * LDH + ldc4 * 4) = pb[j];
        }
    };

    float acc[2][8][4];
#pragma unroll
    for (int mt = 0; mt < 2; mt++)
#pragma unroll
        for (int nt = 0; nt < 8; nt++)
#pragma unroll
            for (int i = 0; i < 4; i++) acc[mt][nt][i] = 0.f;

    const int NC = K >> 5;
    const int arow = wm * 32 + tr;
    const int brow = wn * 64 + tr;

    prefetch(0);
    stage(0);
    __syncthreads();

    for (int c = 0; c < NC; c++) {
        const int b = c & 1;
        if (c + 1 < NC) prefetch((c + 1) << 5);

        const __half* As = Ast[b];
        const __half* Bs = Bst[b];
#pragma unroll
        for (int ks = 0; ks < 2; ks++) {
            const int kh = ks * 16 + 2 * tc;
            uint32_t af[2][4], bf[8][2];
#pragma unroll
            for (int mt = 0; mt < 2; mt++) {
                const __half* p = As + (arow + mt * 16) * LDH + kh;
                af[mt][0] = *(const uint32_t*)(p);
                af[mt][1] = *(const uint32_t*)(p + 8 * LDH);
                af[mt][2] = *(const uint32_t*)(p + 8);
                af[mt][3] = *(const uint32_t*)(p + 8 * LDH + 8);
            }
#pragma unroll
            for (int nt = 0; nt < 8; nt++) {
                const __half* p = Bs + (brow + nt * 8) * LDH + kh;
                bf[nt][0] = *(const uint32_t*)(p);
                bf[nt][1] = *(const uint32_t*)(p + 8);
            }
#pragma unroll
            for (int mt = 0; mt < 2; mt++)
#pragma unroll
                for (int nt = 0; nt < 8; nt++)
                    mma16(acc[mt][nt], af[mt], bf[nt]);
        }

        if (c + 1 < NC) stage(b ^ 1);
        __syncthreads();
    }

    if (S == 0) {
        const int cb = blockIdx.x * 128 + wn * 64;
#pragma unroll
        for (int mt = 0; mt < 2; mt++) {
            const int r0 = row0 + wm * 32 + mt * 16 + tr;
#pragma unroll
            for (int nt = 0; nt < 8; nt++) {
                const int c0 = cb + nt * 8 + 2 * tc;
                if (r0 < Mtot)
                    *(float2*)(Y + (size_t)r0 * ldy + c0) =
                        make_float2(acc[mt][nt][0], acc[mt][nt][1]);
                if (r0 + 8 < Mtot)
                    *(float2*)(Y + (size_t)(r0 + 8) * ldy + c0) =
                        make_float2(acc[mt][nt][2], acc[mt][nt][3]);
            }
        }
    } else {
#pragma unroll
        for (int mt = 0; mt < 2; mt++) {
            const int rr = wm * 32 + mt * 16 + tr;
            const float m0 = msk[rr], m1 = msk[rr + 8];
#pragma unroll
            for (int nt = 0; nt < 8; nt++) {
                const int cc = wn * 64 + nt * 8 + 2 * tc;
                buf[rr * EPI_STRIDE + cc]           = fmaxf(acc[mt][nt][0], 0.f) * m0;
                buf[rr * EPI_STRIDE + cc + 1]       = fmaxf(acc[mt][nt][1], 0.f) * m0;
                buf[(rr + 8) * EPI_STRIDE + cc]     = fmaxf(acc[mt][nt][2], 0.f) * m1;
                buf[(rr + 8) * EPI_STRIDE + cc + 1] = fmaxf(acc[mt][nt][3], 0.f) * m1;
            }
        }
        __syncthreads();
        const int G = Mtot / S;
        for (int tt = t; tt < GPC * 128; tt += 256) {
            const int g = tt >> 7, cc = tt & 127;
            const int og = blockIdx.y * GPC + g;
            if (og < G) {
                float m = 0.f;
#pragma unroll
                for (int r = 0; r < S; r++)
                    m = fmaxf(m, buf[(g * S + r) * EPI_STRIDE + cc]);
                Y[(size_t)og * 256 + blockIdx.x * 128 + cc] = m;
            }
        }
    }
}

// ---------------------------------------------------------------------------
// Small GEMM: CTA 64x64, 128 threads, warp tile 32x32. For M=1024 projections.
// blockIdx.x = N tile, blockIdx.y = M tile.
// ---------------------------------------------------------------------------
__global__ __launch_bounds__(128, 4) void mma_small(
    const float* __restrict__ X, const float* __restrict__ W,
    float* __restrict__ Y, int K, int Mtot, int ldy)
{
    extern __shared__ char smem[];
    __half* Ast[2] = { (__half*)smem, (__half*)(smem + S_STAGE_H) };
    __half* Bst[2] = { (__half*)(smem + 2 * S_STAGE_H),
                       (__half*)(smem + 3 * S_STAGE_H) };

    const int t    = threadIdx.x;
    const int lane = t & 31;
    const int warp = t >> 5;
    const int wm   = warp >> 1;
    const int wn   = warp & 1;
    const int tr   = lane >> 2;
    const int tc   = lane & 3;

    const int row0 = blockIdx.y * 64;
    const float* Wb = W + (size_t)blockIdx.x * 64 * K;

    const int ldrow = t >> 3;            // 0..15 (+ j*16)
    const int ldc4  = t & 7;

    uint2 pa[4], pb[4];
    auto prefetch = [&](int k0) {
#pragma unroll
        for (int j = 0; j < 4; j++) {
            int row = ldrow + j * 16;
            int rg = row0 + row;
            float4 va = (rg < Mtot)
                ? *(const float4*)(X + (size_t)rg * K + k0 + ldc4 * 4)
                : make_float4(0.f, 0.f, 0.f, 0.f);
            float4 vb = *(const float4*)(Wb + (size_t)row * K + k0 + ldc4 * 4);
            pa[j] = make_uint2(h2u(__floats2half2_rn(va.x, va.y)),
                               h2u(__floats2half2_rn(va.z, va.w)));
            pb[j] = make_uint2(h2u(__floats2half2_rn(vb.x, vb.y)),
                               h2u(__floats2half2_rn(vb.z, vb.w)));
        }
    };
    auto stage = [&](int b) {
        __half* As = Ast[b];
        __half* Bs = Bst[b];
#pragma unroll
        for (int j = 0; j < 4; j++) {
            int row = ldrow + j * 16;
            *(uint2*)(As + row * LDH + ldc4 * 4) = pa[j];
            *(uint2*)(Bs + row * LDH + ldc4 * 4) = pb[j];
        }
    };

    float acc[2][4][4];
#pragma unroll
    for (int mt = 0; mt < 2; mt++)
#pragma unroll
        for (int nt = 0; nt < 4; nt++)
#pragma unroll
            for (int i = 0; i < 4; i++) acc[mt][nt][i] = 0.f;

    const int NC = K >> 5;
    const int arow = wm * 32 + tr;
    const int brow = wn * 32 + tr;

    prefetch(0);
    stage(0);
    __syncthreads();

    for (int c = 0; c < NC; c++) {
        const int b = c & 1;
        if (c + 1 < NC) prefetch((c + 1) << 5);

        const __half* As = Ast[b];
        const __half* Bs = Bst[b];
#pragma unroll
        for (int ks = 0; ks < 2; ks++) {
            const int kh = ks * 16 + 2 * tc;
            uint32_t af[2][4], bf[4][2];
#pragma unroll
            for (int mt = 0; mt < 2; mt++) {
                const __half* p = As + (arow + mt * 16) * LDH + kh;
                af[mt][0] = *(const uint32_t*)(p);
                af[mt][1] = *(const uint32_t*)(p + 8 * LDH);
                af[mt][2] = *(const uint32_t*)(p + 8);
                af[mt][3] = *(const uint32_t*)(p + 8 * LDH + 8);
            }
#pragma unroll
            for (int nt = 0; nt < 4; nt++) {
                const __half* p = Bs + (brow + nt * 8) * LDH + kh;
                bf[nt][0] = *(const uint32_t*)(p);
                bf[nt][1] = *(const uint32_t*)(p + 8);
            }
#pragma unroll
            for (int mt = 0; mt < 2; mt++)
#pragma unroll
                for (int nt = 0; nt < 4; nt++)
                    mma16(acc[mt][nt], af[mt], bf[nt]);
        }

        if (c + 1 < NC) stage(b ^ 1);
        __syncthreads();
    }

    const int cb = blockIdx.x * 64 + wn * 32;
#pragma unroll
    for (int mt = 0; mt < 2; mt++) {
        const int r0 = row0 + wm * 32 + mt * 16 + tr;
#pragma unroll
        for (int nt = 0; nt < 4; nt++) {
            const int c0 = cb + nt * 8 + 2 * tc;
            if (r0 < Mtot)
                *(float2*)(Y + (size_t)r0 * ldy + c0) =
                    make_float2(acc[mt][nt][0], acc[mt][nt][1]);
            if (r0 + 8 < Mtot)
                *(float2*)(Y + (size_t)(r0 + 8) * ldy + c0) =
                    make_float2(acc[mt][nt][2], acc[mt][nt][3]);
        }
    }
}

// ---------------------------------------------------------------------------
// Host driver — 10 graph-capturable launches.
// ---------------------------------------------------------------------------
extern "C" void kernel_launch(void* const* d_in, const int* in_sizes, int n_in,
                              void* d_out, int out_size)
{
    const float* h0    = (const float*)d_in[0];
    const float* h1    = (const float*)d_in[1];
    const float* h2    = (const float*)d_in[2];
    const float* mask0 = (const float*)d_in[3];
    const float* mask1 = (const float*)d_in[4];
    const float* Ws0   = (const float*)d_in[5];
    const float* Wn0   = (const float*)d_in[6];
    const float* Wp0   = (const float*)d_in[7];
    const float* Ws1   = (const float*)d_in[8];
    const float* Wn1   = (const float*)d_in[9];
    const float* Wp1   = (const float*)d_in[10];
    const float* Wout  = (const float*)d_in[11];
    float* out = (float*)d_out;

    float *pool1, *pool0, *state1, *state0, *pooled, *fin;
    cudaGetSymbolAddress((void**)&pool1,  g_pool1);
    cudaGetSymbolAddress((void**)&pool0,  g_pool0);
    cudaGetSymbolAddress((void**)&state1, g_state1);
    cudaGetSymbolAddress((void**)&state0, g_state0);
    cudaGetSymbolAddress((void**)&pooled, g_pooled);
    cudaGetSymbolAddress((void**)&fin,    g_fin);

    cudaFuncSetAttribute(mma_big<25>, cudaFuncAttributeMaxDynamicSharedMemorySize, SMEM_BIG);
    cudaFuncSetAttribute(mma_big<10>, cudaFuncAttributeMaxDynamicSharedMemorySize, SMEM_BIG);
    cudaFuncSetAttribute(mma_big<0>,  cudaFuncAttributeMaxDynamicSharedMemorySize, SMEM_BIG);
    cudaFuncSetAttribute(mma_small,   cudaFuncAttributeMaxDynamicSharedMemorySize, SMEM_SMALL);

    const int B = 1024;

    // ---- layer 0 ----
    // pool1 = maxpool_25 relu(h2 @ Wn0^T) * mask1      (B*10, 256)
    mma_big<25><<<dim3(2, 2048), 256, SMEM_BIG>>>(h2, Wn0, mask1, pool1, 256, B * 250, 0);
    // pool0 = maxpool_10 relu(h1 @ Wn0^T) * mask0      (B, 256)
    mma_big<10><<<dim3(2, 86), 256, SMEM_BIG>>>(h1, Wn0, mask0, pool0, 256, B * 10, 0);

    // state1 = concat( h1 @ Ws0^T , pool1 @ Wp0^T )    (B*10, 512)
    mma_big<0><<<dim3(2, 80), 256, SMEM_BIG>>>(h1,    Ws0, nullptr, state1,       256, B * 10, 512);
    mma_big<0><<<dim3(2, 80), 256, SMEM_BIG>>>(pool1, Wp0, nullptr, state1 + 256, 256, B * 10, 512);

    // state0 = concat( h0 @ Ws0^T , pool0 @ Wp0^T )    (B, 512)
    mma_small<<<dim3(4, 16), 128, SMEM_SMALL>>>(h0,    Ws0, state0,       256, B, 512);
    mma_small<<<dim3(4, 16), 128, SMEM_SMALL>>>(pool0, Wp0, state0 + 256, 256, B, 512);

    // ---- layer 1 ----
    // pooled = maxpool_10 relu(state1 @ Wn1^T) * mask0 (B, 256), K=512
    mma_big<10><<<dim3(2, 86), 256, SMEM_BIG>>>(state1, Wn1, mask0, pooled, 512, B * 10, 0);

    // fin = concat( state0 @ Ws1^T , pooled @ Wp1^T )  (B, 512)
    mma_small<<<dim3(4, 16), 128, SMEM_SMALL>>>(state0, Ws1, fin,       512, B, 512);
    mma_small<<<dim3(4, 16), 128, SMEM_SMALL>>>(pooled, Wp1, fin + 256, 256, B, 512);

    // ---- output ----
    mma_small<<<dim3(2, 16), 128, SMEM_SMALL>>>(fin, Wout, out, 512, B, 128);
}

// round 8
// speedup vs baseline: 2.6619x; 1.4408x over previous
#include <cuda_runtime.h>
#include <cuda_fp16.h>
#include <cstdint>

// ---------------------------------------------------------------------------
// GraphSAGE, fp16 mma.sync + ldmatrix + cp.async. B=1024, F=D=256, OUT=128,
// EXP=[10,25]. All weights/inputs pre-converted to fp16 once; intermediates
// stored fp16 (identical rounding count to converting at GEMM read).
// pool_big: CTA 128x128, fused masked-relu-max epilogue.
// gemm64:   CTA 64x64 for all projections (many CTAs -> latency hiding).
// ---------------------------------------------------------------------------

#define LDH 40                         // halves per smem row (80B: 16B-aligned, 20-bank step)
#define STG_H (128 * LDH * 2)          // 10240 B per stage
#define EPI_STRIDE 132
#define SMEM_BIG (1024 + 128 * EPI_STRIDE * 4)   // 68608 (epi dominates stages)
#define S_STG_H (64 * LDH * 2)         // 5120 B
#define SMEM_G64 (4 * S_STG_H)         // 20480

// fp16 scratch (static device globals — no allocation allowed)
__device__ __half g_pool1h [10240 * 256];
__device__ __half g_pool0h [1024  * 256];
__device__ __half g_state1h[10240 * 512];
__device__ __half g_state0h[1024  * 512];
__device__ __half g_pooledh[1024  * 256];
__device__ __half g_finh   [1024  * 512];
__device__ __half g_h0h [1024  * 256];
__device__ __half g_h1h [10240 * 256];
__device__ __half g_Ws0h[256 * 256];
__device__ __half g_Wn0h[256 * 256];
__device__ __half g_Wp0h[256 * 256];
__device__ __half g_Ws1h[256 * 512];
__device__ __half g_Wn1h[256 * 512];
__device__ __half g_Wp1h[256 * 256];
__device__ __half g_Wouth[128 * 512];

__device__ __forceinline__ uint32_t h2u(__half2 h) {
    return *reinterpret_cast<uint32_t*>(&h);
}
__device__ __forceinline__ uint32_t sm32(const void* p) {
    return (uint32_t)__cvta_generic_to_shared(p);
}
__device__ __forceinline__ void cpa16(uint32_t dst, const void* src) {
    asm volatile("cp.async.cg.shared.global [%0], [%1], 16;" :: "r"(dst), "l"(src));
}
#define CP_COMMIT asm volatile("cp.async.commit_group;")
#define CP_WAIT0  asm volatile("cp.async.wait_group 0;")

__device__ __forceinline__ void ldsm4(uint32_t* r, uint32_t addr) {
    asm volatile("ldmatrix.sync.aligned.m8n8.x4.shared.b16 {%0,%1,%2,%3}, [%4];"
        : "=r"(r[0]), "=r"(r[1]), "=r"(r[2]), "=r"(r[3]) : "r"(addr));
}
__device__ __forceinline__ void mma16(float* c, const uint32_t* a, const uint32_t* b) {
    asm volatile(
        "mma.sync.aligned.m16n8k16.row.col.f32.f16.f16.f32 "
        "{%0,%1,%2,%3}, {%4,%5,%6,%7}, {%8,%9}, {%0,%1,%2,%3};"
        : "+f"(c[0]), "+f"(c[1]), "+f"(c[2]), "+f"(c[3])
        : "r"(a[0]), "r"(a[1]), "r"(a[2]), "r"(a[3]), "r"(b[0]), "r"(b[1]));
}

// ---------------------------------------------------------------------------
// conv_all: fp32 -> fp16 for 9 segments (weights + h0 + h1). blockIdx.y = seg.
// ---------------------------------------------------------------------------
struct ConvArgs { const float* s[9]; __half* d[9]; int n[9]; };

__global__ __launch_bounds__(256) void conv_all(ConvArgs a) {
    const int seg = blockIdx.y;
    const int i4 = blockIdx.x * 256 + threadIdx.x;
    if (i4 * 4 >= a.n[seg]) return;
    const float4 v = *(const float4*)(a.s[seg] + (size_t)i4 * 4);
    *(uint2*)(a.d[seg] + (size_t)i4 * 4) =
        make_uint2(h2u(__floats2half2_rn(v.x, v.y)),
                   h2u(__floats2half2_rn(v.z, v.w)));
}

// ---------------------------------------------------------------------------
// pool_big<S, A16>: Y[g, bx*128+n] = max_{s<S} relu(X[gS+s] . W[n]) * mask
// CTA tile 128(M) x 128(N); blockIdx.x = N-half, blockIdx.y = M tile.
// A16: A is fp16 (cp.async); else fp32 (LDG->cvt->STS). B always fp16 cp.async.
// Padded/clamped rows get mask=0 (exact: all pooled candidates >= 0).
// ---------------------------------------------------------------------------
template <int S, bool A16>
__global__ __launch_bounds__(256, 2) void pool_big(
    const void* __restrict__ Xv, const __half* __restrict__ Wh,
    const float* __restrict__ mask, __half* __restrict__ Y,
    int K, int Mtot)
{
    constexpr int RPC = (S == 25) ? 125 : 120;
    constexpr int GPC = RPC / S;

    extern __shared__ char smem[];
    float* msk = (float*)smem;                 // [128]
    float* buf = (float*)(smem + 1024);        // epilogue (overlays stages)
    __half* A_[2] = { (__half*)(smem + 1024), (__half*)(smem + 1024 + STG_H) };
    __half* B_[2] = { (__half*)(smem + 1024 + 2 * STG_H),
                      (__half*)(smem + 1024 + 3 * STG_H) };

    const int t    = threadIdx.x;
    const int lane = t & 31;
    const int warp = t >> 5;
    const int wm   = warp >> 1;
    const int wn   = warp & 1;
    const int tr   = lane >> 2;
    const int tc   = lane & 3;

    const int row0 = blockIdx.y * RPC;
    const __half* Bg = Wh + (size_t)blockIdx.x * 128 * K;
    const float*  Xf = (const float*)Xv;
    const __half* Xh = (const __half*)Xv;

    if (t < 128) {
        int rg = row0 + t;
        msk[t] = (t < RPC && rg < Mtot) ? mask[rg] : 0.f;
    }

    auto issueB = [&](int k0, int b) {
#pragma unroll
        for (int i = 0; i < 2; i++) {
            int s = t + i * 256, r = s >> 2, j = s & 3;
            cpa16(sm32(B_[b] + r * LDH + j * 8), Bg + (size_t)r * K + k0 + j * 8);
        }
    };
    auto issueA16 = [&](int k0, int b) {
#pragma unroll
        for (int i = 0; i < 2; i++) {
            int s = t + i * 256, r = s >> 2, j = s & 3;
            int rg = row0 + r; if (rg >= Mtot) rg = Mtot - 1;
            cpa16(sm32(A_[b] + r * LDH + j * 8), Xh + (size_t)rg * K + k0 + j * 8);
        }
    };
    // fp32 A path: 128 rows x 32 floats; 4 float4 per thread
    float4 pa[4];
    auto prefA = [&](int k0) {
#pragma unroll
        for (int i = 0; i < 4; i++) {
            int s = t + i * 256, r = s >> 3, j = s & 7;
            int rg = row0 + r;
            pa[i] = (rg < Mtot)
                ? *(const float4*)(Xf + (size_t)rg * K + k0 + j * 4)
                : make_float4(0.f, 0.f, 0.f, 0.f);
        }
    };
    auto stageA = [&](int b) {
#pragma unroll
        for (int i = 0; i < 4; i++) {
            int s = t + i * 256, r = s >> 3, j = s & 7;
            *(uint2*)(A_[b] + r * LDH + j * 4) =
                make_uint2(h2u(__floats2half2_rn(pa[i].x, pa[i].y)),
                           h2u(__floats2half2_rn(pa[i].z, pa[i].w)));
        }
    };

    // ldmatrix per-lane offsets (bytes within a stage buffer)
    const int a_r = (lane & 7) + ((lane >> 3) & 1) * 8;
    const int a_c = (lane >> 4) * 8;
    uint32_t aoff[2];
#pragma unroll
    for (int mt = 0; mt < 2; mt++)
        aoff[mt] = ((wm * 32 + mt * 16 + a_r) * LDH + a_c) * 2;
    const int b_r = (lane & 7) + (lane >> 4) * 8;
    const int b_c = ((lane >> 3) & 1) * 8;
    uint32_t boff[4];
#pragma unroll
    for (int np = 0; np < 4; np++)
        boff[np] = ((wn * 64 + np * 16 + b_r) * LDH + b_c) * 2;

    float acc[2][8][4];
#pragma unroll
    for (int mt = 0; mt < 2; mt++)
#pragma unroll
        for (int nt = 0; nt < 8; nt++)
#pragma unroll
            for (int i = 0; i < 4; i++) acc[mt][nt][i] = 0.f;

    const int NC = K >> 5;

    // prologue
    if (A16) issueA16(0, 0); else prefA(0);
    issueB(0, 0); CP_COMMIT;
    if (!A16) stageA(0);
    CP_WAIT0;
    __syncthreads();

    for (int c = 0; c < NC; c++) {
        const int b = c & 1;
        if (c + 1 < NC) {
            if (A16) issueA16((c + 1) << 5, b ^ 1); else prefA((c + 1) << 5);
            issueB((c + 1) << 5, b ^ 1);
            CP_COMMIT;
        }

        const uint32_t a_sm = sm32(A_[b]);
        const uint32_t b_sm = sm32(B_[b]);
#pragma unroll
        for (int ks = 0; ks < 2; ks++) {
            const int khb = ks * 32;   // kh*2 bytes
            uint32_t af[2][4], bq[4][4];
            ldsm4(af[0], a_sm + aoff[0] + khb);
            ldsm4(af[1], a_sm + aoff[1] + khb);
#pragma unroll
            for (int np = 0; np < 4; np++)
                ldsm4(bq[np], b_sm + boff[np] + khb);
#pragma unroll
            for (int mt = 0; mt < 2; mt++)
#pragma unroll
                for (int np = 0; np < 4; np++) {
                    mma16(acc[mt][2 * np],     af[mt], &bq[np][0]);
                    mma16(acc[mt][2 * np + 1], af[mt], &bq[np][2]);
                }
        }

        if (c + 1 < NC) {
            if (!A16) stageA(b ^ 1);
            CP_WAIT0;
        }
        __syncthreads();
    }

    // fused masked-relu-max epilogue
#pragma unroll
    for (int mt = 0; mt < 2; mt++) {
        const int rr = wm * 32 + mt * 16 + tr;
        const float m0 = msk[rr], m1 = msk[rr + 8];
#pragma unroll
        for (int nt = 0; nt < 8; nt++) {
            const int cc = wn * 64 + nt * 8 + 2 * tc;
            buf[rr * EPI_STRIDE + cc]           = fmaxf(acc[mt][nt][0], 0.f) * m0;
            buf[rr * EPI_STRIDE + cc + 1]       = fmaxf(acc[mt][nt][1], 0.f) * m0;
            buf[(rr + 8) * EPI_STRIDE + cc]     = fmaxf(acc[mt][nt][2], 0.f) * m1;
            buf[(rr + 8) * EPI_STRIDE + cc + 1] = fmaxf(acc[mt][nt][3], 0.f) * m1;
        }
    }
    __syncthreads();
    const int G = Mtot / S;
    for (int tt = t; tt < GPC * 128; tt += 256) {
        const int g = tt >> 7, cc = tt & 127;
        const int og = blockIdx.y * GPC + g;
        if (og < G) {
            float m = 0.f;
#pragma unroll
            for (int r = 0; r < S; r++)
                m = fmaxf(m, buf[(g * S + r) * EPI_STRIDE + cc]);
            Y[(size_t)og * 256 + blockIdx.x * 128 + cc] = __float2half(m);
        }
    }
}

// ---------------------------------------------------------------------------
// gemm64<OUTF32>: Y = X @ W^T, CTA 64x64, 128 threads, fp16 A/B via cp.async.
// blockIdx.x = N tile, blockIdx.y = M tile. M, N exact multiples of 64.
// ---------------------------------------------------------------------------
template <bool OUTF32>
__global__ __launch_bounds__(128, 5) void gemm64(
    const __half* __restrict__ X, const __half* __restrict__ W,
    void* __restrict__ Yv, int K, int ldy)
{
    extern __shared__ char smem[];
    __half* A_[2] = { (__half*)smem, (__half*)(smem + S_STG_H) };
    __half* B_[2] = { (__half*)(smem + 2 * S_STG_H), (__half*)(smem + 3 * S_STG_H) };

    const int t    = threadIdx.x;
    const int lane = t & 31;
    const int warp = t >> 5;
    const int wm   = warp >> 1;
    const int wn   = warp & 1;
    const int tr   = lane >> 2;
    const int tc   = lane & 3;

    const int row0 = blockIdx.y * 64;
    const __half* Bg = W + (size_t)blockIdx.x * 64 * K;

    auto issue = [&](int k0, int b) {
#pragma unroll
        for (int i = 0; i < 2; i++) {
            int s = t + i * 128, r = s >> 2, j = s & 3;
            cpa16(sm32(A_[b] + r * LDH + j * 8),
                  X + (size_t)(row0 + r) * K + k0 + j * 8);
            cpa16(sm32(B_[b] + r * LDH + j * 8), Bg + (size_t)r * K + k0 + j * 8);
        }
    };

    const int a_r = (lane & 7) + ((lane >> 3) & 1) * 8;
    const int a_c = (lane >> 4) * 8;
    uint32_t aoff[2];
#pragma unroll
    for (int mt = 0; mt < 2; mt++)
        aoff[mt] = ((wm * 32 + mt * 16 + a_r) * LDH + a_c) * 2;
    const int b_r = (lane & 7) + (lane >> 4) * 8;
    const int b_c = ((lane >> 3) & 1) * 8;
    uint32_t boff[2];
#pragma unroll
    for (int np = 0; np < 2; np++)
        boff[np] = ((wn * 32 + np * 16 + b_r) * LDH + b_c) * 2;

    float acc[2][4][4];
#pragma unroll
    for (int mt = 0; mt < 2; mt++)
#pragma unroll
        for (int nt = 0; nt < 4; nt++)
#pragma unroll
            for (int i = 0; i < 4; i++) acc[mt][nt][i] = 0.f;

    const int NC = K >> 5;
    issue(0, 0); CP_COMMIT;
    CP_WAIT0;
    __syncthreads();

    for (int c = 0; c < NC; c++) {
        const int b = c & 1;
        if (c + 1 < NC) { issue((c + 1) << 5, b ^ 1); CP_COMMIT; }

        const uint32_t a_sm = sm32(A_[b]);
        const uint32_t b_sm = sm32(B_[b]);
#pragma unroll
        for (int ks = 0; ks < 2; ks++) {
            const int khb = ks * 32;
            uint32_t af[2][4], bq[2][4];
            ldsm4(af[0], a_sm + aoff[0] + khb);
            ldsm4(af[1], a_sm + aoff[1] + khb);
            ldsm4(bq[0], b_sm + boff[0] + khb);
            ldsm4(bq[1], b_sm + boff[1] + khb);
#pragma unroll
            for (int mt = 0; mt < 2; mt++)
#pragma unroll
                for (int np = 0; np < 2; np++) {
                    mma16(acc[mt][2 * np],     af[mt], &bq[np][0]);
                    mma16(acc[mt][2 * np + 1], af[mt], &bq[np][2]);
                }
        }

        if (c + 1 < NC) CP_WAIT0;
        __syncthreads();
    }

    const int cb = blockIdx.x * 64 + wn * 32;
#pragma unroll
    for (int mt = 0; mt < 2; mt++) {
        const int r0 = row0 + wm * 32 + mt * 16 + tr;
#pragma unroll
        for (int nt = 0; nt < 4; nt++) {
            const int c0 = cb + nt * 8 + 2 * tc;
            if (OUTF32) {
                float* Y = (float*)Yv;
                *(float2*)(Y + (size_t)r0 * ldy + c0) =
                    make_float2(acc[mt][nt][0], acc[mt][nt][1]);
                *(float2*)(Y + (size_t)(r0 + 8) * ldy + c0) =
                    make_float2(acc[mt][nt][2], acc[mt][nt][3]);
            } else {
                __half* Y = (__half*)Yv;
                *(uint32_t*)(Y + (size_t)r0 * ldy + c0) =
                    h2u(__floats2half2_rn(acc[mt][nt][0], acc[mt][nt][1]));
                *(uint32_t*)(Y + (size_t)(r0 + 8) * ldy + c0) =
                    h2u(__floats2half2_rn(acc[mt][nt][2], acc[mt][nt][3]));
            }
        }
    }
}

// ---------------------------------------------------------------------------
// Host driver — 11 graph-capturable launches.
// ---------------------------------------------------------------------------
extern "C" void kernel_launch(void* const* d_in, const int* in_sizes, int n_in,
                              void* d_out, int out_size)
{
    const float* h0    = (const float*)d_in[0];
    const float* h1    = (const float*)d_in[1];
    const float* h2    = (const float*)d_in[2];
    const float* mask0 = (const float*)d_in[3];
    const float* mask1 = (const float*)d_in[4];
    const float* Ws0   = (const float*)d_in[5];
    const float* Wn0   = (const float*)d_in[6];
    const float* Wp0   = (const float*)d_in[7];
    const float* Ws1   = (const float*)d_in[8];
    const float* Wn1   = (const float*)d_in[9];
    const float* Wp1   = (const float*)d_in[10];
    const float* Wout  = (const float*)d_in[11];
    float* out = (float*)d_out;

    __half *pool1, *pool0, *state1, *state0, *pooled, *fin;
    __half *h0h, *h1h, *ws0, *wn0, *wp0, *ws1, *wn1, *wp1, *wo;
    cudaGetSymbolAddress((void**)&pool1,  g_pool1h);
    cudaGetSymbolAddress((void**)&pool0,  g_pool0h);
    cudaGetSymbolAddress((void**)&state1, g_state1h);
    cudaGetSymbolAddress((void**)&state0, g_state0h);
    cudaGetSymbolAddress((void**)&pooled, g_pooledh);
    cudaGetSymbolAddress((void**)&fin,    g_finh);
    cudaGetSymbolAddress((void**)&h0h, g_h0h);
    cudaGetSymbolAddress((void**)&h1h, g_h1h);
    cudaGetSymbolAddress((void**)&ws0, g_Ws0h);
    cudaGetSymbolAddress((void**)&wn0, g_Wn0h);
    cudaGetSymbolAddress((void**)&wp0, g_Wp0h);
    cudaGetSymbolAddress((void**)&ws1, g_Ws1h);
    cudaGetSymbolAddress((void**)&wn1, g_Wn1h);
    cudaGetSymbolAddress((void**)&wp1, g_Wp1h);
    cudaGetSymbolAddress((void**)&wo,  g_Wouth);

    cudaFuncSetAttribute(pool_big<25, false>, cudaFuncAttributeMaxDynamicSharedMemorySize, SMEM_BIG);
    cudaFuncSetAttribute(pool_big<10, true>,  cudaFuncAttributeMaxDynamicSharedMemorySize, SMEM_BIG);
    cudaFuncSetAttribute(gemm64<false>, cudaFuncAttributeMaxDynamicSharedMemorySize, SMEM_G64);
    cudaFuncSetAttribute(gemm64<true>,  cudaFuncAttributeMaxDynamicSharedMemorySize, SMEM_G64);

    const int B = 1024;

    // ---- fp32 -> fp16 conversions (one launch) ----
    ConvArgs ca;
    ca.s[0] = h0;  ca.d[0] = h0h; ca.n[0] = 1024 * 256;
    ca.s[1] = h1;  ca.d[1] = h1h; ca.n[1] = 10240 * 256;
    ca.s[2] = Ws0; ca.d[2] = ws0; ca.n[2] = 256 * 256;
    ca.s[3] = Wn0; ca.d[3] = wn0; ca.n[3] = 256 * 256;
    ca.s[4] = Wp0; ca.d[4] = wp0; ca.n[4] = 256 * 256;
    ca.s[5] = Ws1; ca.d[5] = ws1; ca.n[5] = 256 * 512;
    ca.s[6] = Wn1; ca.d[6] = wn1; ca.n[6] = 256 * 512;
    ca.s[7] = Wp1; ca.d[7] = wp1; ca.n[7] = 256 * 256;
    ca.s[8] = Wout; ca.d[8] = wo; ca.n[8] = 128 * 512;
    conv_all<<<dim3(2560, 9), 256>>>(ca);

    // ---- layer 0 ----
    pool_big<25, false><<<dim3(2, 2048), 256, SMEM_BIG>>>(h2, wn0, mask1, pool1, 256, B * 250);
    pool_big<10, true ><<<dim3(2, 86),   256, SMEM_BIG>>>(h1h, wn0, mask0, pool0, 256, B * 10);

    gemm64<false><<<dim3(4, 160), 128, SMEM_G64>>>(h1h,   ws0, state1,       256, 512);
    gemm64<false><<<dim3(4, 160), 128, SMEM_G64>>>(pool1, wp0, state1 + 256, 256, 512);
    gemm64<false><<<dim3(4, 16),  128, SMEM_G64>>>(h0h,   ws0, state0,       256, 512);
    gemm64<false><<<dim3(4, 16),  128, SMEM_G64>>>(pool0, wp0, state0 + 256, 256, 512);

    // ---- layer 1 ----
    pool_big<10, true><<<dim3(2, 86), 256, SMEM_BIG>>>(state1, wn1, mask0, pooled, 512, B * 10);

    gemm64<false><<<dim3(4, 16), 128, SMEM_G64>>>(state0, ws1, fin,       512, 512);
    gemm64<false><<<dim3(4, 16), 128, SMEM_G64>>>(pooled, wp1, fin + 256, 256, 512);

    // ---- output (fp32) ----
    gemm64<true><<<dim3(2, 16), 128, SMEM_G64>>>(fin, wo, out, 512, 128);
}

// round 11
// speedup vs baseline: 2.7466x; 1.0318x over previous
#include <cuda_runtime.h>
#include <cuda_fp16.h>
#include <cstdint>

// ---------------------------------------------------------------------------
// GraphSAGE, fp16 mma.sync + ldmatrix + 3-stage cp.async. B=1024, F=D=256,
// OUT=128, EXP=[10,25]. Weights/inputs pre-converted fp16; intermediates fp16.
// pool_big: CTA 128x128 fused masked-relu-max. gemm64: 64x64 projections,
// pair-fused via blockIdx.z.
// ---------------------------------------------------------------------------

#define LDH 40                          // halves per fp16 smem row
#define LDF 36                          // floats per fp32 smem row (144B, 16B-aligned)
#define BSTG (128 * LDH * 2)            // 10240 B  (B stage, 128 rows x 32 halves)
#define ASTG16 (128 * LDH * 2)          // 10240 B  (A fp16 stage)
#define ASTG32 (128 * LDF * 4)          // 18432 B  (A fp32 stage)
#define EPI_STRIDE 132
#define SMEM_P25 (1024 + 3 * ASTG32 + 3 * BSTG)          // 87040
#define SMEM_P10 (1024 + 128 * EPI_STRIDE * 4)           // 68608 (epi > stages)
#define S_STG (64 * LDH * 2)            // 5120
#define SMEM_G64 (6 * S_STG)            // 30720

// fp16 scratch (static device globals — no allocation allowed)
__device__ __half g_pool1h [10240 * 256];
__device__ __half g_pool0h [1024  * 256];
__device__ __half g_state1h[10240 * 512];
__device__ __half g_state0h[1024  * 512];
__device__ __half g_pooledh[1024  * 256];
__device__ __half g_finh   [1024  * 512];
__device__ __half g_h0h [1024  * 256];
__device__ __half g_h1h [10240 * 256];
__device__ __half g_Ws0h[256 * 256];
__device__ __half g_Wn0h[256 * 256];
__device__ __half g_Wp0h[256 * 256];
__device__ __half g_Ws1h[256 * 512];
__device__ __half g_Wn1h[256 * 512];
__device__ __half g_Wp1h[256 * 256];
__device__ __half g_Wouth[128 * 512];

__device__ __forceinline__ uint32_t h2u(__half2 h) {
    return *reinterpret_cast<uint32_t*>(&h);
}
__device__ __forceinline__ uint32_t sm32(const void* p) {
    return (uint32_t)__cvta_generic_to_shared(p);
}
__device__ __forceinline__ void cpa16(uint32_t dst, const void* src) {
    asm volatile("cp.async.cg.shared.global [%0], [%1], 16;" :: "r"(dst), "l"(src));
}
#define CP_COMMIT asm volatile("cp.async.commit_group;")
#define CP_WAIT0  asm volatile("cp.async.wait_group 0;")
#define CP_WAIT1  asm volatile("cp.async.wait_group 1;")

__device__ __forceinline__ void ldsm4(uint32_t* r, uint32_t addr) {
    asm volatile("ldmatrix.sync.aligned.m8n8.x4.shared.b16 {%0,%1,%2,%3}, [%4];"
        : "=r"(r[0]), "=r"(r[1]), "=r"(r[2]), "=r"(r[3]) : "r"(addr));
}
__device__ __forceinline__ void mma16(float* c, const uint32_t* a, const uint32_t* b) {
    asm volatile(
        "mma.sync.aligned.m16n8k16.row.col.f32.f16.f16.f32 "
        "{%0,%1,%2,%3}, {%4,%5,%6,%7}, {%8,%9}, {%0,%1,%2,%3};"
        : "+f"(c[0]), "+f"(c[1]), "+f"(c[2]), "+f"(c[3])
        : "r"(a[0]), "r"(a[1]), "r"(a[2]), "r"(a[3]), "r"(b[0]), "r"(b[1]));
}

// ---------------------------------------------------------------------------
// conv_all: fp32 -> fp16, 9 segments. blockIdx.y = segment.
// ---------------------------------------------------------------------------
struct ConvArgs { const float* s[9]; __half* d[9]; int n[9]; };

__global__ __launch_bounds__(256) void conv_all(ConvArgs a) {
    const int seg = blockIdx.y;
    const int i4 = blockIdx.x * 256 + threadIdx.x;
    if (i4 * 4 >= a.n[seg]) return;
    const float4 v = *(const float4*)(a.s[seg] + (size_t)i4 * 4);
    *(uint2*)(a.d[seg] + (size_t)i4 * 4) =
        make_uint2(h2u(__floats2half2_rn(v.x, v.y)),
                   h2u(__floats2half2_rn(v.z, v.w)));
}

// ---------------------------------------------------------------------------
// pool_big<S, A16>: Y[g, bx*128+n] = max_{s<S} relu(X[gS+s] . W[n]) * mask
// 3-stage cp.async. A16: A fp16 from smem via ldmatrix. !A16: A fp32 via
// cp.async, fragments read with LDS.64 + cvt. Clamped rows get mask=0 (exact).
// ---------------------------------------------------------------------------
template <int S, bool A16>
__global__ __launch_bounds__(256, 2) void pool_big(
    const void* __restrict__ Xv, const __half* __restrict__ Wh,
    const float* __restrict__ mask, __half* __restrict__ Y,
    int K, int Mtot)
{
    constexpr int RPC = (S == 25) ? 125 : 120;
    constexpr int GPC = RPC / S;
    constexpr int ASTG = A16 ? ASTG16 : ASTG32;

    extern __shared__ char smem[];
    float* msk = (float*)smem;
    float* buf = (float*)(smem + 1024);
    char* Abase = smem + 1024;
    char* Bbase = smem + 1024 + 3 * ASTG;

    const int t    = threadIdx.x;
    const int lane = t & 31;
    const int warp = t >> 5;
    const int wm   = warp >> 1;
    const int wn   = warp & 1;
    const int tr   = lane >> 2;
    const int tc   = lane & 3;

    const int row0 = blockIdx.y * RPC;
    const __half* Bg = Wh + (size_t)blockIdx.x * 128 * K;
    const float*  Xf = (const float*)Xv;
    const __half* Xh = (const __half*)Xv;

    if (t < 128) {
        int rg = row0 + t;
        msk[t] = (t < RPC && rg < Mtot) ? mask[rg] : 0.f;
    }

    auto issue = [&](int c, int st) {
        const int k0 = c << 5;
        char* Af = Abase + st * ASTG;
        char* Bf = Bbase + st * BSTG;
        if (A16) {
#pragma unroll
            for (int i = 0; i < 2; i++) {
                int s = t + i * 256, r = s >> 2, j = s & 3;
                int rg = row0 + r; if (rg >= Mtot) rg = Mtot - 1;
                cpa16(sm32((__half*)Af + r * LDH + j * 8),
                      Xh + (size_t)rg * K + k0 + j * 8);
            }
        } else {
#pragma unroll
            for (int i = 0; i < 4; i++) {
                int s = t + i * 256, r = s >> 3, j = s & 7;
                int rg = row0 + r; if (rg >= Mtot) rg = Mtot - 1;
                cpa16(sm32((float*)Af + r * LDF + j * 4),
                      Xf + (size_t)rg * K + k0 + j * 4);
            }
        }
#pragma unroll
        for (int i = 0; i < 2; i++) {
            int s = t + i * 256, r = s >> 2, j = s & 3;
            cpa16(sm32((__half*)Bf + r * LDH + j * 8),
                  Bg + (size_t)r * K + k0 + j * 8);
        }
        CP_COMMIT;
    };

    // fragment address prep
    const int a_r = (lane & 7) + ((lane >> 3) & 1) * 8;
    const int a_c = (lane >> 4) * 8;
    uint32_t aoff[2];
#pragma unroll
    for (int mt = 0; mt < 2; mt++)
        aoff[mt] = ((wm * 32 + mt * 16 + a_r) * LDH + a_c) * 2;   // A16 path
    const int b_r = (lane & 7) + (lane >> 4) * 8;
    const int b_c = ((lane >> 3) & 1) * 8;
    uint32_t boff[4];
#pragma unroll
    for (int np = 0; np < 4; np++)
        boff[np] = ((wn * 64 + np * 16 + b_r) * LDH + b_c) * 2;

    float acc[2][8][4];
#pragma unroll
    for (int mt = 0; mt < 2; mt++)
#pragma unroll
        for (int nt = 0; nt < 8; nt++)
#pragma unroll
            for (int i = 0; i < 4; i++) acc[mt][nt][i] = 0.f;

    const int NC = K >> 5;

    issue(0, 0);
    issue(1, 1);
    CP_WAIT1;
    __syncthreads();

    for (int c = 0; c < NC; c++) {
        const int st = c % 3;
        if (c + 2 < NC) issue(c + 2, (c + 2) % 3);

        const char* Af = Abase + st * ASTG;
        const uint32_t b_sm = sm32(Bbase + st * BSTG);
#pragma unroll
        for (int ks = 0; ks < 2; ks++) {
            uint32_t af[2][4], bq[4][4];
            if (A16) {
                const uint32_t a_sm = sm32(Af);
                ldsm4(af[0], a_sm + aoff[0] + ks * 32);
                ldsm4(af[1], a_sm + aoff[1] + ks * 32);
            } else {
                const float* As = (const float*)Af;
                const int kc = ks * 16 + 2 * tc;
#pragma unroll
                for (int mt = 0; mt < 2; mt++) {
                    const float* p = As + (wm * 32 + mt * 16 + tr) * LDF + kc;
                    float2 v00 = *(const float2*)(p);
                    float2 v10 = *(const float2*)(p + 8 * LDF);
                    float2 v01 = *(const float2*)(p + 8);
                    float2 v11 = *(const float2*)(p + 8 * LDF + 8);
                    af[mt][0] = h2u(__floats2half2_rn(v00.x, v00.y));
                    af[mt][1] = h2u(__floats2half2_rn(v10.x, v10.y));
                    af[mt][2] = h2u(__floats2half2_rn(v01.x, v01.y));
                    af[mt][3] = h2u(__floats2half2_rn(v11.x, v11.y));
                }
            }
#pragma unroll
            for (int np = 0; np < 4; np++)
                ldsm4(bq[np], b_sm + boff[np] + ks * 32);
#pragma unroll
            for (int mt = 0; mt < 2; mt++)
#pragma unroll
                for (int np = 0; np < 4; np++) {
                    mma16(acc[mt][2 * np],     af[mt], &bq[np][0]);
                    mma16(acc[mt][2 * np + 1], af[mt], &bq[np][2]);
                }
        }

        if (c + 2 < NC)       { CP_WAIT1; }
        else if (c + 1 < NC)  { CP_WAIT0; }
        __syncthreads();
    }

    // fused masked-relu-max epilogue
#pragma unroll
    for (int mt = 0; mt < 2; mt++) {
        const int rr = wm * 32 + mt * 16 + tr;
        const float m0 = msk[rr], m1 = msk[rr + 8];
#pragma unroll
        for (int nt = 0; nt < 8; nt++) {
            const int cc = wn * 64 + nt * 8 + 2 * tc;
            buf[rr * EPI_STRIDE + cc]           = fmaxf(acc[mt][nt][0], 0.f) * m0;
            buf[rr * EPI_STRIDE + cc + 1]       = fmaxf(acc[mt][nt][1], 0.f) * m0;
            buf[(rr + 8) * EPI_STRIDE + cc]     = fmaxf(acc[mt][nt][2], 0.f) * m1;
            buf[(rr + 8) * EPI_STRIDE + cc + 1] = fmaxf(acc[mt][nt][3], 0.f) * m1;
        }
    }
    __syncthreads();
    const int G = Mtot / S;
    for (int tt = t; tt < GPC * 128; tt += 256) {
        const int g = tt >> 7, cc = tt & 127;
        const int og = blockIdx.y * GPC + g;
        if (og < G) {
            float m = 0.f;
#pragma unroll
            for (int r = 0; r < S; r++)
                m = fmaxf(m, buf[(g * S + r) * EPI_STRIDE + cc]);
            Y[(size_t)og * 256 + blockIdx.x * 128 + cc] = __float2half(m);
        }
    }
}

// ---------------------------------------------------------------------------
// gemm64 core: one 64x64 tile, 3-stage cp.async, fp16 in, out fp16 or fp32.
// ---------------------------------------------------------------------------
template <bool OUTF32>
__device__ __forceinline__ void gemm64_body(
    const __half* __restrict__ X, const __half* __restrict__ W,
    void* __restrict__ Yv, int K, int ldy, char* smem)
{
    __half* A_[3] = { (__half*)smem, (__half*)(smem + S_STG), (__half*)(smem + 2 * S_STG) };
    __half* B_[3] = { (__half*)(smem + 3 * S_STG), (__half*)(smem + 4 * S_STG),
                      (__half*)(smem + 5 * S_STG) };

    const int t    = threadIdx.x;
    const int lane = t & 31;
    const int warp = t >> 5;
    const int wm   = warp >> 1;
    const int wn   = warp & 1;
    const int tr   = lane >> 2;
    const int tc   = lane & 3;

    const int row0 = blockIdx.y * 64;
    const __half* Bg = W + (size_t)blockIdx.x * 64 * K;

    auto issue = [&](int c, int st) {
        const int k0 = c << 5;
#pragma unroll
        for (int i = 0; i < 2; i++) {
            int s = t + i * 128, r = s >> 2, j = s & 3;
            cpa16(sm32(A_[st] + r * LDH + j * 8),
                  X + (size_t)(row0 + r) * K + k0 + j * 8);
            cpa16(sm32(B_[st] + r * LDH + j * 8), Bg + (size_t)r * K + k0 + j * 8);
        }
        CP_COMMIT;
    };

    const int a_r = (lane & 7) + ((lane >> 3) & 1) * 8;
    const int a_c = (lane >> 4) * 8;
    uint32_t aoff[2];
#pragma unroll
    for (int mt = 0; mt < 2; mt++)
        aoff[mt] = ((wm * 32 + mt * 16 + a_r) * LDH + a_c) * 2;
    const int b_r = (lane & 7) + (lane >> 4) * 8;
    const int b_c = ((lane >> 3) & 1) * 8;
    uint32_t boff[2];
#pragma unroll
    for (int np = 0; np < 2; np++)
        boff[np] = ((wn * 32 + np * 16 + b_r) * LDH + b_c) * 2;

    float acc[2][4][4];
#pragma unroll
    for (int mt = 0; mt < 2; mt++)
#pragma unroll
        for (int nt = 0; nt < 4; nt++)
#pragma unroll
            for (int i = 0; i < 4; i++) acc[mt][nt][i] = 0.f;

    const int NC = K >> 5;
    issue(0, 0);
    issue(1, 1);
    CP_WAIT1;
    __syncthreads();

    for (int c = 0; c < NC; c++) {
        const int st = c % 3;
        if (c + 2 < NC) issue(c + 2, (c + 2) % 3);

        const uint32_t a_sm = sm32(A_[st]);
        const uint32_t b_sm = sm32(B_[st]);
#pragma unroll
        for (int ks = 0; ks < 2; ks++) {
            uint32_t af[2][4], bq[2][4];
            ldsm4(af[0], a_sm + aoff[0] + ks * 32);
            ldsm4(af[1], a_sm + aoff[1] + ks * 32);
            ldsm4(bq[0], b_sm + boff[0] + ks * 32);
            ldsm4(bq[1], b_sm + boff[1] + ks * 32);
#pragma unroll
            for (int mt = 0; mt < 2; mt++)
#pragma unroll
                for (int np = 0; np < 2; np++) {
                    mma16(acc[mt][2 * np],     af[mt], &bq[np][0]);
                    mma16(acc[mt][2 * np + 1], af[mt], &bq[np][2]);
                }
        }

        if (c + 2 < NC)      { CP_WAIT1; }
        else if (c + 1 < NC) { CP_WAIT0; }
        __syncthreads();
    }

    const int cb = blockIdx.x * 64 + wn * 32;
#pragma unroll
    for (int mt = 0; mt < 2; mt++) {
        const int r0 = row0 + wm * 32 + mt * 16 + tr;
#pragma unroll
        for (int nt = 0; nt < 4; nt++) {
            const int c0 = cb + nt * 8 + 2 * tc;
            if (OUTF32) {
                float* Y = (float*)Yv;
                *(float2*)(Y + (size_t)r0 * ldy + c0) =
                    make_float2(acc[mt][nt][0], acc[mt][nt][1]);
                *(float2*)(Y + (size_t)(r0 + 8) * ldy + c0) =
                    make_float2(acc[mt][nt][2], acc[mt][nt][3]);
            } else {
                __half* Y = (__half*)Yv;
                *(uint32_t*)(Y + (size_t)r0 * ldy + c0) =
                    h2u(__floats2half2_rn(acc[mt][nt][0], acc[mt][nt][1]));
                *(uint32_t*)(Y + (size_t)(r0 + 8) * ldy + c0) =
                    h2u(__floats2half2_rn(acc[mt][nt][2], acc[mt][nt][3]));
            }
        }
    }
}

// pair kernel: blockIdx.z selects one of two GEMMs (both ldy=512, fp16 out)
struct PairArgs {
    const __half *X0, *W0; __half *Y0; int K0;
    const __half *X1, *W1; __half *Y1; int K1;
};

__global__ __launch_bounds__(128, 5) void gemm64_pair(PairArgs a) {
    extern __shared__ char smem[];
    if (blockIdx.z == 0)
        gemm64_body<false>(a.X0, a.W0, a.Y0, a.K0, 512, smem);
    else
        gemm64_body<false>(a.X1, a.W1, a.Y1, a.K1, 512, smem);
}

__global__ __launch_bounds__(128, 5) void gemm64_out(
    const __half* X, const __half* W, float* Y, int K, int ldy) {
    extern __shared__ char smem[];
    gemm64_body<true>(X, W, Y, K, ldy, smem);
}

// ---------------------------------------------------------------------------
// Host driver — 8 graph-capturable launches.
// ---------------------------------------------------------------------------
extern "C" void kernel_launch(void* const* d_in, const int* in_sizes, int n_in,
                              void* d_out, int out_size)
{
    const float* h0    = (const float*)d_in[0];
    const float* h1    = (const float*)d_in[1];
    const float* h2    = (const float*)d_in[2];
    const float* mask0 = (const float*)d_in[3];
    const float* mask1 = (const float*)d_in[4];
    const float* Ws0   = (const float*)d_in[5];
    const float* Wn0   = (const float*)d_in[6];
    const float* Wp0   = (const float*)d_in[7];
    const float* Ws1   = (const float*)d_in[8];
    const float* Wn1   = (const float*)d_in[9];
    const float* Wp1   = (const float*)d_in[10];
    const float* Wout  = (const float*)d_in[11];
    float* out = (float*)d_out;

    __half *pool1, *pool0, *state1, *state0, *pooled, *fin;
    __half *h0h, *h1h, *ws0, *wn0, *wp0, *ws1, *wn1, *wp1, *wo;
    cudaGetSymbolAddress((void**)&pool1,  g_pool1h);
    cudaGetSymbolAddress((void**)&pool0,  g_pool0h);
    cudaGetSymbolAddress((void**)&state1, g_state1h);
    cudaGetSymbolAddress((void**)&state0, g_state0h);
    cudaGetSymbolAddress((void**)&pooled, g_pooledh);
    cudaGetSymbolAddress((void**)&fin,    g_finh);
    cudaGetSymbolAddress((void**)&h0h, g_h0h);
    cudaGetSymbolAddress((void**)&h1h, g_h1h);
    cudaGetSymbolAddress((void**)&ws0, g_Ws0h);
    cudaGetSymbolAddress((void**)&wn0, g_Wn0h);
    cudaGetSymbolAddress((void**)&wp0, g_Wp0h);
    cudaGetSymbolAddress((void**)&ws1, g_Ws1h);
    cudaGetSymbolAddress((void**)&wn1, g_Wn1h);
    cudaGetSymbolAddress((void**)&wp1, g_Wp1h);
    cudaGetSymbolAddress((void**)&wo,  g_Wouth);

    cudaFuncSetAttribute(pool_big<25, false>, cudaFuncAttributeMaxDynamicSharedMemorySize, SMEM_P25);
    cudaFuncSetAttribute(pool_big<10, true>,  cudaFuncAttributeMaxDynamicSharedMemorySize, SMEM_P10);
    cudaFuncSetAttribute(gemm64_pair, cudaFuncAttributeMaxDynamicSharedMemorySize, SMEM_G64);
    cudaFuncSetAttribute(gemm64_out,  cudaFuncAttributeMaxDynamicSharedMemorySize, SMEM_G64);

    const int B = 1024;

    // ---- fp32 -> fp16 conversions ----
    ConvArgs ca;
    ca.s[0] = h0;  ca.d[0] = h0h; ca.n[0] = 1024 * 256;
    ca.s[1] = h1;  ca.d[1] = h1h; ca.n[1] = 10240 * 256;
    ca.s[2] = Ws0; ca.d[2] = ws0; ca.n[2] = 256 * 256;
    ca.s[3] = Wn0; ca.d[3] = wn0; ca.n[3] = 256 * 256;
    ca.s[4] = Wp0; ca.d[4] = wp0; ca.n[4] = 256 * 256;
    ca.s[5] = Ws1; ca.d[5] = ws1; ca.n[5] = 256 * 512;
    ca.s[6] = Wn1; ca.d[6] = wn1; ca.n[6] = 256 * 512;
    ca.s[7] = Wp1; ca.d[7] = wp1; ca.n[7] = 256 * 256;
    ca.s[8] = Wout; ca.d[8] = wo; ca.n[8] = 128 * 512;
    conv_all<<<dim3(2560, 9), 256>>>(ca);

    // ---- layer 0 pools ----
    pool_big<25, false><<<dim3(2, 2048), 256, SMEM_P25>>>(h2, wn0, mask1, pool1, 256, B * 250);
    pool_big<10, true ><<<dim3(2, 86),   256, SMEM_P10>>>(h1h, wn0, mask0, pool0, 256, B * 10);

    // state1 = concat(h1@Ws0^T, pool1@Wp0^T) (10240, 512)
    {
        PairArgs a = { h1h, ws0, state1, 256, pool1, wp0, state1 + 256, 256 };
        gemm64_pair<<<dim3(4, 160, 2), 128, SMEM_G64>>>(a);
    }
    // state0 = concat(h0@Ws0^T, pool0@Wp0^T) (1024, 512)
    {
        PairArgs a = { h0h, ws0, state0, 256, pool0, wp0, state0 + 256, 256 };
        gemm64_pair<<<dim3(4, 16, 2), 128, SMEM_G64>>>(a);
    }

    // ---- layer 1 pool ----
    pool_big<10, true><<<dim3(2, 86), 256, SMEM_P10>>>(state1, wn1, mask0, pooled, 512, B * 10);

    // fin = concat(state0@Ws1^T, pooled@Wp1^T) (1024, 512)
    {
        PairArgs a = { state0, ws1, fin, 512, pooled, wp1, fin + 256, 256 };
        gemm64_pair<<<dim3(4, 16, 2), 128, SMEM_G64>>>(a);
    }

    // ---- output (fp32) ----
    gemm64_out<<<dim3(2, 16), 128, SMEM_G64>>>(fin, wo, out, 512, 128);
}

// round 12
// speedup vs baseline: 2.8202x; 1.0268x over previous
#include <cuda_runtime.h>
#include <cuda_fp16.h>
#include <cstdint>

// ---------------------------------------------------------------------------
// GraphSAGE, fp16 mma.sync + ldmatrix + cp.async pipelines.
// B=1024, F=D=256, OUT=128, EXP=[10,25].
// pool25 (fp32 A): K-chunk 64, 2-stage (chunk compute >= DRAM latency).
// pool10 / gemm64 (fp16): K-chunk 32, 4-stage (lookahead 2 chunks).
// ---------------------------------------------------------------------------

#define LDH 40                          // halves per fp16 smem row (K32 stage)
#define LDB64 72                        // halves per fp16 smem row (K64 stage)
#define LDF 68                          // floats per fp32 smem row (K64 stage)
#define EPI_STRIDE 132

#define A32STG (128 * LDF * 4)          // 34816
#define B64STG (128 * LDB64 * 2)        // 18432
#define A16STG (128 * LDH * 2)          // 10240
#define SMEM_P25 (1024 + 2 * A32STG + 2 * B64STG)    // 107520
#define SMEM_P10 (1024 + 8 * A16STG)                 // 82944 (>= epi 67584+1024)
#define S_STG (64 * LDH * 2)            // 5120
#define SMEM_G64 (8 * S_STG)            // 40960 (4 stages)

// fp16 scratch (static device globals — no allocation allowed)
__device__ __half g_pool1h [10240 * 256];
__device__ __half g_pool0h [1024  * 256];
__device__ __half g_state1h[10240 * 512];
__device__ __half g_state0h[1024  * 512];
__device__ __half g_pooledh[1024  * 256];
__device__ __half g_finh   [1024  * 512];
__device__ __half g_h0h [1024  * 256];
__device__ __half g_h1h [10240 * 256];
__device__ __half g_Ws0h[256 * 256];
__device__ __half g_Wn0h[256 * 256];
__device__ __half g_Wp0h[256 * 256];
__device__ __half g_Ws1h[256 * 512];
__device__ __half g_Wn1h[256 * 512];
__device__ __half g_Wp1h[256 * 256];
__device__ __half g_Wouth[128 * 512];

__device__ __forceinline__ uint32_t h2u(__half2 h) {
    return *reinterpret_cast<uint32_t*>(&h);
}
__device__ __forceinline__ uint32_t sm32(const void* p) {
    return (uint32_t)__cvta_generic_to_shared(p);
}
__device__ __forceinline__ void cpa16(uint32_t dst, const void* src) {
    asm volatile("cp.async.cg.shared.global [%0], [%1], 16;" :: "r"(dst), "l"(src));
}
#define CP_COMMIT asm volatile("cp.async.commit_group;")
__device__ __forceinline__ void cp_wait_dyn(int n) {
    if (n <= 0)      asm volatile("cp.async.wait_group 0;");
    else if (n == 1) asm volatile("cp.async.wait_group 1;");
    else             asm volatile("cp.async.wait_group 2;");
}

__device__ __forceinline__ void ldsm4(uint32_t* r, uint32_t addr) {
    asm volatile("ldmatrix.sync.aligned.m8n8.x4.shared.b16 {%0,%1,%2,%3}, [%4];"
        : "=r"(r[0]), "=r"(r[1]), "=r"(r[2]), "=r"(r[3]) : "r"(addr));
}
__device__ __forceinline__ void mma16(float* c, const uint32_t* a, const uint32_t* b) {
    asm volatile(
        "mma.sync.aligned.m16n8k16.row.col.f32.f16.f16.f32 "
        "{%0,%1,%2,%3}, {%4,%5,%6,%7}, {%8,%9}, {%0,%1,%2,%3};"
        : "+f"(c[0]), "+f"(c[1]), "+f"(c[2]), "+f"(c[3])
        : "r"(a[0]), "r"(a[1]), "r"(a[2]), "r"(a[3]), "r"(b[0]), "r"(b[1]));
}

// ---------------------------------------------------------------------------
// conv_all: fp32 -> fp16, 9 segments. blockIdx.y = segment.
// ---------------------------------------------------------------------------
struct ConvArgs { const float* s[9]; __half* d[9]; int n[9]; };

__global__ __launch_bounds__(256) void conv_all(ConvArgs a) {
    const int seg = blockIdx.y;
    const int i4 = blockIdx.x * 256 + threadIdx.x;
    if (i4 * 4 >= a.n[seg]) return;
    const float4 v = *(const float4*)(a.s[seg] + (size_t)i4 * 4);
    *(uint2*)(a.d[seg] + (size_t)i4 * 4) =
        make_uint2(h2u(__floats2half2_rn(v.x, v.y)),
                   h2u(__floats2half2_rn(v.z, v.w)));
}

// ---------------------------------------------------------------------------
// pool_big<S, A16>: Y[g, bx*128+n] = max_{s<S} relu(X[gS+s] . W[n]) * mask
// A16: fp16 A, K-chunk 32, 4 stages. !A16: fp32 A, K-chunk 64, 2 stages.
// Clamped/padded rows get mask=0 (exact: all pooled candidates >= 0).
// ---------------------------------------------------------------------------
template <int S, bool A16>
__global__ __launch_bounds__(256, 2) void pool_big(
    const void* __restrict__ Xv, const __half* __restrict__ Wh,
    const float* __restrict__ mask, __half* __restrict__ Y,
    int K, int Mtot)
{
    constexpr int RPC  = (S == 25) ? 125 : 120;
    constexpr int GPC  = RPC / S;
    constexpr int NSTG = A16 ? 4 : 2;
    constexpr int CK   = A16 ? 32 : 64;          // K per chunk
    constexpr int ASTG = A16 ? A16STG : A32STG;
    constexpr int BSTG = A16 ? A16STG : B64STG;
    constexpr int LDB  = A16 ? LDH : LDB64;

    extern __shared__ char smem[];
    float* msk = (float*)smem;
    float* buf = (float*)(smem + 1024);
    char* Abase = smem + 1024;
    char* Bbase = smem + 1024 + NSTG * ASTG;

    const int t    = threadIdx.x;
    const int lane = t & 31;
    const int warp = t >> 5;
    const int wm   = warp >> 1;
    const int wn   = warp & 1;
    const int tr   = lane >> 2;
    const int tc   = lane & 3;

    const int row0 = blockIdx.y * RPC;
    const __half* Bg = Wh + (size_t)blockIdx.x * 128 * K;
    const float*  Xf = (const float*)Xv;
    const __half* Xh = (const __half*)Xv;

    if (t < 128) {
        int rg = row0 + t;
        msk[t] = (t < RPC && rg < Mtot) ? mask[rg] : 0.f;
    }

    auto issue = [&](int c, int st) {
        const int k0 = c * CK;
        char* Af = Abase + st * ASTG;
        char* Bf = Bbase + st * BSTG;
        if (A16) {
#pragma unroll
            for (int i = 0; i < 2; i++) {
                int s = t + i * 256, r = s >> 2, j = s & 3;
                int rg = row0 + r; if (rg >= Mtot) rg = Mtot - 1;
                cpa16(sm32((__half*)Af + r * LDH + j * 8),
                      Xh + (size_t)rg * K + k0 + j * 8);
            }
#pragma unroll
            for (int i = 0; i < 2; i++) {
                int s = t + i * 256, r = s >> 2, j = s & 3;
                cpa16(sm32((__half*)Bf + r * LDH + j * 8),
                      Bg + (size_t)r * K + k0 + j * 8);
            }
        } else {
            // A: 128 rows x 16 float4
#pragma unroll
            for (int i = 0; i < 8; i++) {
                int s = t + i * 256, r = s >> 4, j = s & 15;
                int rg = row0 + r; if (rg >= Mtot) rg = Mtot - 1;
                cpa16(sm32((float*)Af + r * LDF + j * 4),
                      Xf + (size_t)rg * K + k0 + j * 4);
            }
            // B: 128 rows x 8 halves-16B
#pragma unroll
            for (int i = 0; i < 4; i++) {
                int s = t + i * 256, r = s >> 3, j = s & 7;
                cpa16(sm32((__half*)Bf + r * LDB64 + j * 8),
                      Bg + (size_t)r * K + k0 + j * 8);
            }
        }
        CP_COMMIT;
    };

    const int a_r = (lane & 7) + ((lane >> 3) & 1) * 8;
    const int a_c = (lane >> 4) * 8;
    uint32_t aoff[2];
#pragma unroll
    for (int mt = 0; mt < 2; mt++)
        aoff[mt] = ((wm * 32 + mt * 16 + a_r) * LDH + a_c) * 2;   // A16 path
    const int b_r = (lane & 7) + (lane >> 4) * 8;
    const int b_c = ((lane >> 3) & 1) * 8;
    uint32_t boff[4];
#pragma unroll
    for (int np = 0; np < 4; np++)
        boff[np] = ((wn * 64 + np * 16 + b_r) * LDB + b_c) * 2;

    float acc[2][8][4];
#pragma unroll
    for (int mt = 0; mt < 2; mt++)
#pragma unroll
        for (int nt = 0; nt < 8; nt++)
#pragma unroll
            for (int i = 0; i < 4; i++) acc[mt][nt][i] = 0.f;

    const int NC = K / CK;

#pragma unroll
    for (int s = 0; s < NSTG - 1; s++) issue(s, s);
    cp_wait_dyn(NSTG - 2);
    __syncthreads();

    for (int c = 0; c < NC; c++) {
        const int st = c % NSTG;
        if (c + NSTG - 1 < NC) issue(c + NSTG - 1, (c + NSTG - 1) % NSTG);

        const char* Af = Abase + st * ASTG;
        const uint32_t b_sm = sm32(Bbase + st * BSTG);
#pragma unroll
        for (int ks = 0; ks < CK / 16; ks++) {
            uint32_t af[2][4], bq[4][4];
            if (A16) {
                const uint32_t a_sm = sm32(Af);
                ldsm4(af[0], a_sm + aoff[0] + ks * 32);
                ldsm4(af[1], a_sm + aoff[1] + ks * 32);
            } else {
                const float* As = (const float*)Af;
                const int kc = ks * 16 + 2 * tc;
#pragma unroll
                for (int mt = 0; mt < 2; mt++) {
                    const float* p = As + (wm * 32 + mt * 16 + tr) * LDF + kc;
                    float2 v00 = *(const float2*)(p);
                    float2 v10 = *(const float2*)(p + 8 * LDF);
                    float2 v01 = *(const float2*)(p + 8);
                    float2 v11 = *(const float2*)(p + 8 * LDF + 8);
                    af[mt][0] = h2u(__floats2half2_rn(v00.x, v00.y));
                    af[mt][1] = h2u(__floats2half2_rn(v10.x, v10.y));
                    af[mt][2] = h2u(__floats2half2_rn(v01.x, v01.y));
                    af[mt][3] = h2u(__floats2half2_rn(v11.x, v11.y));
                }
            }
#pragma unroll
            for (int np = 0; np < 4; np++)
                ldsm4(bq[np], b_sm + boff[np] + ks * 32);
#pragma unroll
            for (int mt = 0; mt < 2; mt++)
#pragma unroll
                for (int np = 0; np < 4; np++) {
                    mma16(acc[mt][2 * np],     af[mt], &bq[np][0]);
                    mma16(acc[mt][2 * np + 1], af[mt], &bq[np][2]);
                }
        }

        if (c + 1 < NC) {
            int last_issued = min(NC - 1, c + NSTG - 1);
            cp_wait_dyn(last_issued - (c + 1));
            __syncthreads();
        } else {
            __syncthreads();   // all warps done reading stages before epilogue reuse
        }
    }

    // fused masked-relu-max epilogue
#pragma unroll
    for (int mt = 0; mt < 2; mt++) {
        const int rr = wm * 32 + mt * 16 + tr;
        const float m0 = msk[rr], m1 = msk[rr + 8];
#pragma unroll
        for (int nt = 0; nt < 8; nt++) {
            const int cc = wn * 64 + nt * 8 + 2 * tc;
            buf[rr * EPI_STRIDE + cc]           = fmaxf(acc[mt][nt][0], 0.f) * m0;
            buf[rr * EPI_STRIDE + cc + 1]       = fmaxf(acc[mt][nt][1], 0.f) * m0;
            buf[(rr + 8) * EPI_STRIDE + cc]     = fmaxf(acc[mt][nt][2], 0.f) * m1;
            buf[(rr + 8) * EPI_STRIDE + cc + 1] = fmaxf(acc[mt][nt][3], 0.f) * m1;
        }
    }
    __syncthreads();
    const int G = Mtot / S;
    for (int tt = t; tt < GPC * 128; tt += 256) {
        const int g = tt >> 7, cc = tt & 127;
        const int og = blockIdx.y * GPC + g;
        if (og < G) {
            float m = 0.f;
#pragma unroll
            for (int r = 0; r < S; r++)
                m = fmaxf(m, buf[(g * S + r) * EPI_STRIDE + cc]);
            Y[(size_t)og * 256 + blockIdx.x * 128 + cc] = __float2half(m);
        }
    }
}

// ---------------------------------------------------------------------------
// gemm64 core: one 64x64 tile, 4-stage cp.async, fp16 in, out fp16 or fp32.
// ---------------------------------------------------------------------------
template <bool OUTF32>
__device__ __forceinline__ void gemm64_body(
    const __half* __restrict__ X, const __half* __restrict__ W,
    void* __restrict__ Yv, int K, int ldy, char* smem)
{
    const int t    = threadIdx.x;
    const int lane = t & 31;
    const int warp = t >> 5;
    const int wm   = warp >> 1;
    const int wn   = warp & 1;
    const int tr   = lane >> 2;
    const int tc   = lane & 3;

    const int row0 = blockIdx.y * 64;
    const __half* Bg = W + (size_t)blockIdx.x * 64 * K;

    auto A_ = [&](int st) { return (__half*)(smem + st * S_STG); };
    auto B_ = [&](int st) { return (__half*)(smem + (4 + st) * S_STG); };

    auto issue = [&](int c, int st) {
        const int k0 = c << 5;
#pragma unroll
        for (int i = 0; i < 2; i++) {
            int s = t + i * 128, r = s >> 2, j = s & 3;
            cpa16(sm32(A_(st) + r * LDH + j * 8),
                  X + (size_t)(row0 + r) * K + k0 + j * 8);
            cpa16(sm32(B_(st) + r * LDH + j * 8), Bg + (size_t)r * K + k0 + j * 8);
        }
        CP_COMMIT;
    };

    const int a_r = (lane & 7) + ((lane >> 3) & 1) * 8;
    const int a_c = (lane >> 4) * 8;
    uint32_t aoff[2];
#pragma unroll
    for (int mt = 0; mt < 2; mt++)
        aoff[mt] = ((wm * 32 + mt * 16 + a_r) * LDH + a_c) * 2;
    const int b_r = (lane & 7) + (lane >> 4) * 8;
    const int b_c = ((lane >> 3) & 1) * 8;
    uint32_t boff[2];
#pragma unroll
    for (int np = 0; np < 2; np++)
        boff[np] = ((wn * 32 + np * 16 + b_r) * LDH + b_c) * 2;

    float acc[2][4][4];
#pragma unroll
    for (int mt = 0; mt < 2; mt++)
#pragma unroll
        for (int nt = 0; nt < 4; nt++)
#pragma unroll
            for (int i = 0; i < 4; i++) acc[mt][nt][i] = 0.f;

    const int NC = K >> 5;
    issue(0, 0); issue(1, 1); issue(2, 2);
    cp_wait_dyn(2);
    __syncthreads();

    for (int c = 0; c < NC; c++) {
        const int st = c & 3;
        if (c + 3 < NC) issue(c + 3, (c + 3) & 3);

        const uint32_t a_sm = sm32(A_(st));
        const uint32_t b_sm = sm32(B_(st));
#pragma unroll
        for (int ks = 0; ks < 2; ks++) {
            uint32_t af[2][4], bq[2][4];
            ldsm4(af[0], a_sm + aoff[0] + ks * 32);
            ldsm4(af[1], a_sm + aoff[1] + ks * 32);
            ldsm4(bq[0], b_sm + boff[0] + ks * 32);
            ldsm4(bq[1], b_sm + boff[1] + ks * 32);
#pragma unroll
            for (int mt = 0; mt < 2; mt++)
#pragma unroll
                for (int np = 0; np < 2; np++) {
                    mma16(acc[mt][2 * np],     af[mt], &bq[np][0]);
                    mma16(acc[mt][2 * np + 1], af[mt], &bq[np][2]);
                }
        }

        if (c + 1 < NC) {
            int last_issued = min(NC - 1, c + 3);
            cp_wait_dyn(last_issued - (c + 1));
        }
        __syncthreads();
    }

    const int cb = blockIdx.x * 64 + wn * 32;
#pragma unroll
    for (int mt = 0; mt < 2; mt++) {
        const int r0 = row0 + wm * 32 + mt * 16 + tr;
#pragma unroll
        for (int nt = 0; nt < 4; nt++) {
            const int c0 = cb + nt * 8 + 2 * tc;
            if (OUTF32) {
                float* Y = (float*)Yv;
                *(float2*)(Y + (size_t)r0 * ldy + c0) =
                    make_float2(acc[mt][nt][0], acc[mt][nt][1]);
                *(float2*)(Y + (size_t)(r0 + 8) * ldy + c0) =
                    make_float2(acc[mt][nt][2], acc[mt][nt][3]);
            } else {
                __half* Y = (__half*)Yv;
                *(uint32_t*)(Y + (size_t)r0 * ldy + c0) =
                    h2u(__floats2half2_rn(acc[mt][nt][0], acc[mt][nt][1]));
                *(uint32_t*)(Y + (size_t)(r0 + 8) * ldy + c0) =
                    h2u(__floats2half2_rn(acc[mt][nt][2], acc[mt][nt][3]));
            }
        }
    }
}

struct PairArgs {
    const __half *X0, *W0; __half *Y0; int K0;
    const __half *X1, *W1; __half *Y1; int K1;
};

__global__ __launch_bounds__(128, 4) void gemm64_pair(PairArgs a) {
    extern __shared__ char smem[];
    if (blockIdx.z == 0)
        gemm64_body<false>(a.X0, a.W0, a.Y0, a.K0, 512, smem);
    else
        gemm64_body<false>(a.X1, a.W1, a.Y1, a.K1, 512, smem);
}

__global__ __launch_bounds__(128, 4) void gemm64_out(
    const __half* X, const __half* W, float* Y, int K, int ldy) {
    extern __shared__ char smem[];
    gemm64_body<true>(X, W, Y, K, ldy, smem);
}

// ---------------------------------------------------------------------------
// Host driver — 8 graph-capturable launches.
// ---------------------------------------------------------------------------
extern "C" void kernel_launch(void* const* d_in, const int* in_sizes, int n_in,
                              void* d_out, int out_size)
{
    const float* h0    = (const float*)d_in[0];
    const float* h1    = (const float*)d_in[1];
    const float* h2    = (const float*)d_in[2];
    const float* mask0 = (const float*)d_in[3];
    const float* mask1 = (const float*)d_in[4];
    const float* Ws0   = (const float*)d_in[5];
    const float* Wn0   = (const float*)d_in[6];
    const float* Wp0   = (const float*)d_in[7];
    const float* Ws1   = (const float*)d_in[8];
    const float* Wn1   = (const float*)d_in[9];
    const float* Wp1   = (const float*)d_in[10];
    const float* Wout  = (const float*)d_in[11];
    float* out = (float*)d_out;

    __half *pool1, *pool0, *state1, *state0, *pooled, *fin;
    __half *h0h, *h1h, *ws0, *wn0, *wp0, *ws1, *wn1, *wp1, *wo;
    cudaGetSymbolAddress((void**)&pool1,  g_pool1h);
    cudaGetSymbolAddress((void**)&pool0,  g_pool0h);
    cudaGetSymbolAddress((void**)&state1, g_state1h);
    cudaGetSymbolAddress((void**)&state0, g_state0h);
    cudaGetSymbolAddress((void**)&pooled, g_pooledh);
    cudaGetSymbolAddress((void**)&fin,    g_finh);
    cudaGetSymbolAddress((void**)&h0h, g_h0h);
    cudaGetSymbolAddress((void**)&h1h, g_h1h);
    cudaGetSymbolAddress((void**)&ws0, g_Ws0h);
    cudaGetSymbolAddress((void**)&wn0, g_Wn0h);
    cudaGetSymbolAddress((void**)&wp0, g_Wp0h);
    cudaGetSymbolAddress((void**)&ws1, g_Ws1h);
    cudaGetSymbolAddress((void**)&wn1, g_Wn1h);
    cudaGetSymbolAddress((void**)&wp1, g_Wp1h);
    cudaGetSymbolAddress((void**)&wo,  g_Wouth);

    cudaFuncSetAttribute(pool_big<25, false>, cudaFuncAttributeMaxDynamicSharedMemorySize, SMEM_P25);
    cudaFuncSetAttribute(pool_big<10, true>,  cudaFuncAttributeMaxDynamicSharedMemorySize, SMEM_P10);
    cudaFuncSetAttribute(gemm64_pair, cudaFuncAttributeMaxDynamicSharedMemorySize, SMEM_G64);
    cudaFuncSetAttribute(gemm64_out,  cudaFuncAttributeMaxDynamicSharedMemorySize, SMEM_G64);

    const int B = 1024;

    // ---- fp32 -> fp16 conversions ----
    ConvArgs ca;
    ca.s[0] = h0;  ca.d[0] = h0h; ca.n[0] = 1024 * 256;
    ca.s[1] = h1;  ca.d[1] = h1h; ca.n[1] = 10240 * 256;
    ca.s[2] = Ws0; ca.d[2] = ws0; ca.n[2] = 256 * 256;
    ca.s[3] = Wn0; ca.d[3] = wn0; ca.n[3] = 256 * 256;
    ca.s[4] = Wp0; ca.d[4] = wp0; ca.n[4] = 256 * 256;
    ca.s[5] = Ws1; ca.d[5] = ws1; ca.n[5] = 256 * 512;
    ca.s[6] = Wn1; ca.d[6] = wn1; ca.n[6] = 256 * 512;
    ca.s[7] = Wp1; ca.d[7] = wp1; ca.n[7] = 256 * 256;
    ca.s[8] = Wout; ca.d[8] = wo; ca.n[8] = 128 * 512;
    conv_all<<<dim3(2560, 9), 256>>>(ca);

    // ---- layer 0 pools ----
    pool_big<25, false><<<dim3(2, 2048), 256, SMEM_P25>>>(h2, wn0, mask1, pool1, 256, B * 250);
    pool_big<10, true ><<<dim3(2, 86),   256, SMEM_P10>>>(h1h, wn0, mask0, pool0, 256, B * 10);

    // state1 = concat(h1@Ws0^T, pool1@Wp0^T) (10240, 512)
    {
        PairArgs a = { h1h, ws0, state1, 256, pool1, wp0, state1 + 256, 256 };
        gemm64_pair<<<dim3(4, 160, 2), 128, SMEM_G64>>>(a);
    }
    // state0 = concat(h0@Ws0^T, pool0@Wp0^T) (1024, 512)
    {
        PairArgs a = { h0h, ws0, state0, 256, pool0, wp0, state0 + 256, 256 };
        gemm64_pair<<<dim3(4, 16, 2), 128, SMEM_G64>>>(a);
    }

    // ---- layer 1 pool ----
    pool_big<10, true><<<dim3(2, 86), 256, SMEM_P10>>>(state1, wn1, mask0, pooled, 512, B * 10);

    // fin = concat(state0@Ws1^T, pooled@Wp1^T) (1024, 512)
    {
        PairArgs a = { state0, ws1, fin, 512, pooled, wp1, fin + 256, 256 };
        gemm64_pair<<<dim3(4, 16, 2), 128, SMEM_G64>>>(a);
    }

    // ---- output (fp32) ----
    gemm64_out<<<dim3(2, 16), 128, SMEM_G64>>>(fin, wo, out, 512, 128);
}